// round 6
// baseline (speedup 1.0000x reference)
#include <cuda_runtime.h>
#include <math.h>

#define B_ 2
#define N_ 65536
#define DP 64
#define DM 128
#define NPTS (B_*N_)
#define NCHUNK 64
#define SCALE_F 0.088388347648318441f  /* 1/sqrt(128) */

// ---------------- device scratch (no allocations allowed) ----------------
__device__ float g_gv[(size_t)NPTS * DM];   // v + pos_enc   (64 MB)
__device__ float g_Ws[DP * DM];             // fc1 @ (wq - wk)
__device__ float g_Wv[DP * DM];             // fc1 @ wv
__device__ float g_bs[DM];
__device__ float g_bv[DM];
__device__ float g_part[B_ * DM * NCHUNK * 2];
__device__ float g_ms[B_ * DM * 2];

// ---------------- packed f32x2 helpers (sm_103a FFMA2) ----------------
__device__ __forceinline__ unsigned long long pk2(float x, float y) {
    unsigned long long r;
    asm("mov.b64 %0, {%1, %2};" : "=l"(r) : "f"(x), "f"(y));
    return r;
}
__device__ __forceinline__ void fma2(unsigned long long& d,
                                     unsigned long long a, unsigned long long b) {
    asm("fma.rn.f32x2 %0, %1, %2, %0;" : "+l"(d) : "l"(a), "l"(b));
}
__device__ __forceinline__ void upk2(unsigned long long v, float& x, float& y) {
    asm("mov.b64 {%0, %1}, %2;" : "=f"(x), "=f"(y) : "l"(v));
}

// ---------------- k0: fold fc1 into (wq-wk) and wv ----------------
__global__ void k0_fold(const float* __restrict__ fc1w, const float* __restrict__ fc1b,
                        const float* __restrict__ wq, const float* __restrict__ wk,
                        const float* __restrict__ wv)
{
    int idx = blockIdx.x * 256 + threadIdx.x;     // 0..8191
    int m = idx >> 7, j = idx & 127;
    float as = 0.f, av = 0.f;
    for (int k = 0; k < DM; k++) {
        float f = fc1w[m * DM + k];
        as += f * (wq[k * DM + j] - wk[k * DM + j]);
        av += f * wv[k * DM + j];
    }
    g_Ws[idx] = as;
    g_Wv[idx] = av;
    if (blockIdx.x == 0 && threadIdx.x < DM) {
        int jj = threadIdx.x;
        float bs = 0.f, bv = 0.f;
        for (int k = 0; k < DM; k++) {
            float fb = fc1b[k];
            bs += fb * (wq[k * DM + jj] - wk[k * DM + jj]);
            bv += fb * wv[k * DM + jj];
        }
        g_bs[jj] = bs;
        g_bv[jj] = bv;
    }
}

// ---------------- shared GEMM tile: 8x8 outputs per thread, FFMA2 ----------
// W has row stride ldw (floats); c0 must be 8-float (32B) aligned.
__device__ __forceinline__ void gemm_tile2(const float* __restrict__ A, int lda,
                                           const float* __restrict__ W, int ldw, int K,
                                           int r0, int c0, float acc[8][8])
{
    unsigned long long acc2[8][4];
    #pragma unroll
    for (int i = 0; i < 8; i++)
        #pragma unroll
        for (int j = 0; j < 4; j++) acc2[i][j] = 0ull;

    #pragma unroll 2
    for (int k = 0; k < K; k += 2) {
        ulonglong2 w00 = *(const ulonglong2*)(W + (size_t)k * ldw + c0);
        ulonglong2 w01 = *(const ulonglong2*)(W + (size_t)k * ldw + c0 + 4);
        ulonglong2 w10 = *(const ulonglong2*)(W + (size_t)(k + 1) * ldw + c0);
        ulonglong2 w11 = *(const ulonglong2*)(W + (size_t)(k + 1) * ldw + c0 + 4);
        #pragma unroll
        for (int i = 0; i < 8; i++) {
            float2 a2 = *(const float2*)(A + (r0 + i) * lda + k);
            unsigned long long a0 = pk2(a2.x, a2.x);
            unsigned long long a1 = pk2(a2.y, a2.y);
            fma2(acc2[i][0], a0, w00.x); fma2(acc2[i][1], a0, w00.y);
            fma2(acc2[i][2], a0, w01.x); fma2(acc2[i][3], a0, w01.y);
            fma2(acc2[i][0], a1, w10.x); fma2(acc2[i][1], a1, w10.y);
            fma2(acc2[i][2], a1, w11.x); fma2(acc2[i][3], a1, w11.y);
        }
    }
    #pragma unroll
    for (int i = 0; i < 8; i++)
        #pragma unroll
        for (int j = 0; j < 4; j++)
            upk2(acc2[i][j], acc[i][2 * j], acc[i][2 * j + 1]);
}

// ---------------- k1: main per-point chain (128 points / CTA) ----------------
__global__ void __launch_bounds__(256) k1_main(
    const float* __restrict__ xyz, const float* __restrict__ feat,
    const float* __restrict__ d1w, const float* __restrict__ d1b,
    const float* __restrict__ d2w, const float* __restrict__ d2b,
    const float* __restrict__ g1w, const float* __restrict__ g1b,
    const float* __restrict__ g2w, const float* __restrict__ g2b,
    float* __restrict__ aout)
{
    extern __shared__ float smd[];
    float* Wsm = smd;            // 128*128
    float* Pm  = smd + 16384;    // 128*128 : pos, then S
    float* Tm  = smd + 32768;    // 128*128 : hrel, then features, then H
    __shared__ float d1s[384], xyzs[384];
    __shared__ float bd1[DM], bd2[DM], bg1[DM], bg2[DM], bss[DM], bvv[DM];

    const int tid = threadIdx.x;
    const int tx = tid & 15, ty = tid >> 4;
    const int r0 = ty * 8, c0 = tx * 8;
    const int p0 = blockIdx.x * 128;

    for (int i = tid; i < 384; i += 256) { d1s[i] = d1w[i]; xyzs[i] = xyz[p0 * 3 + i]; }
    if (tid < DM) {
        bd1[tid] = d1b[tid]; bd2[tid] = d2b[tid];
        bg1[tid] = g1b[tid]; bg2[tid] = g2b[tid];
        bss[tid] = g_bs[tid]; bvv[tid] = g_bv[tid];
    }
    for (int i = tid * 4; i < 16384; i += 1024)
        *(float4*)(Wsm + i) = *(const float4*)(d2w + i);
    __syncthreads();

    // hrel = relu(xyz @ d1 + d1b)  -> Tm
    #pragma unroll
    for (int i = 0; i < 8; i++) {
        int p = r0 + i;
        float x0 = xyzs[p * 3], x1 = xyzs[p * 3 + 1], x2 = xyzs[p * 3 + 2];
        #pragma unroll
        for (int j = 0; j < 8; j++) {
            int c = c0 + j;
            float h = x0 * d1s[c] + x1 * d1s[DM + c] + x2 * d1s[2 * DM + c] + bd1[c];
            Tm[p * DM + c] = fmaxf(h, 0.f);
        }
    }
    __syncthreads();

    float acc[8][8];

    // pos = hrel @ d2 + d2b  -> Pm
    gemm_tile2(Tm, DM, Wsm, DM, DM, r0, c0, acc);
    #pragma unroll
    for (int i = 0; i < 8; i++)
        #pragma unroll
        for (int j = 0; j < 8; j++)
            Pm[(r0 + i) * DM + c0 + j] = acc[i][j] + bd2[c0 + j];
    __syncthreads();

    // load features tile (128x64) -> Tm, Wv -> Wsm
    for (int i = tid * 4; i < 8192; i += 1024) {
        *(float4*)(Tm + i)  = *(const float4*)(feat + p0 * 64 + i);
        *(float4*)(Wsm + i) = *(const float4*)(g_Wv + i);
    }
    __syncthreads();

    // gv = f @ Wv + bv + pos  -> global
    gemm_tile2(Tm, 64, Wsm, DM, 64, r0, c0, acc);
    #pragma unroll
    for (int i = 0; i < 8; i++)
        #pragma unroll
        for (int j = 0; j < 8; j++)
            g_gv[(size_t)(p0 + r0 + i) * DM + c0 + j] =
                acc[i][j] + bvv[c0 + j] + Pm[(r0 + i) * DM + c0 + j];
    __syncthreads();

    for (int i = tid * 4; i < 8192; i += 1024)
        *(float4*)(Wsm + i) = *(const float4*)(g_Ws + i);
    __syncthreads();

    // S = f @ Ws + bs + pos  -> Pm (each thread RMWs only its own elements)
    gemm_tile2(Tm, 64, Wsm, DM, 64, r0, c0, acc);
    #pragma unroll
    for (int i = 0; i < 8; i++)
        #pragma unroll
        for (int j = 0; j < 8; j++) {
            int o = (r0 + i) * DM + c0 + j;
            Pm[o] = acc[i][j] + bss[c0 + j] + Pm[o];
        }
    __syncthreads();

    for (int i = tid * 4; i < 16384; i += 1024)
        *(float4*)(Wsm + i) = *(const float4*)(g1w + i);
    __syncthreads();

    // H = relu(S @ g1 + g1b) -> Tm
    gemm_tile2(Pm, DM, Wsm, DM, DM, r0, c0, acc);
    #pragma unroll
    for (int i = 0; i < 8; i++)
        #pragma unroll
        for (int j = 0; j < 8; j++)
            Tm[(r0 + i) * DM + c0 + j] = fmaxf(acc[i][j] + bg1[c0 + j], 0.f);
    __syncthreads();

    for (int i = tid * 4; i < 16384; i += 1024)
        *(float4*)(Wsm + i) = *(const float4*)(g2w + i);
    __syncthreads();

    // A = (H @ g2 + g2b) * SCALE -> aout (pre-softmax logits, in-place later)
    gemm_tile2(Tm, DM, Wsm, DM, DM, r0, c0, acc);
    #pragma unroll
    for (int i = 0; i < 8; i++)
        #pragma unroll
        for (int j = 0; j < 8; j++)
            aout[(size_t)(p0 + r0 + i) * DM + c0 + j] =
                (acc[i][j] + bg2[c0 + j]) * SCALE_F;
}

// ---------------- k2a: per-chunk online (max,sum) over N ----------------
__global__ void k2a_stats(const float* __restrict__ aout)
{
    int tx = threadIdx.x, ty = threadIdx.y;
    int c = blockIdx.x * 32 + tx;
    int chunk = blockIdx.y;
    int b = blockIdx.z;
    const float* base = aout + (size_t)b * N_ * DM + c;
    const int rows = N_ / NCHUNK;         // 1024
    int n0 = chunk * rows;

    float m = -3.4e38f, s = 0.f;
    #pragma unroll 4
    for (int n = n0 + ty; n < n0 + rows; n += 8) {
        float a = base[(size_t)n * DM];
        float nm = fmaxf(m, a);
        s = s * __expf(m - nm) + __expf(a - nm);
        m = nm;
    }
    __shared__ float smm[8][32], sms[8][32];
    smm[ty][tx] = m; sms[ty][tx] = s;
    __syncthreads();
    if (ty == 0) {
        float M = m, S = s;
        #pragma unroll
        for (int r = 1; r < 8; r++) {
            float m2 = smm[r][tx], s2 = sms[r][tx];
            float nM = fmaxf(M, m2);
            S = S * __expf(M - nM) + s2 * __expf(m2 - nM);
            M = nM;
        }
        int o = ((b * DM + c) * NCHUNK + chunk) * 2;
        g_part[o] = M; g_part[o + 1] = S;
    }
}

// ---------------- k2b: combine chunk partials (one warp per (b,c)) ---------
__global__ void k2b_combine()
{
    int warp = (blockIdx.x * blockDim.x + threadIdx.x) >> 5;  // 0..255
    int lane = threadIdx.x & 31;
    const float* p = g_part + (size_t)warp * NCHUNK * 2;
    float m1 = p[lane * 2],       s1 = p[lane * 2 + 1];
    float m2 = p[(lane + 32) * 2], s2 = p[(lane + 32) * 2 + 1];
    float M = fmaxf(m1, m2);
    #pragma unroll
    for (int o = 16; o; o >>= 1) M = fmaxf(M, __shfl_xor_sync(0xffffffffu, M, o));
    float S = s1 * __expf(m1 - M) + s2 * __expf(m2 - M);
    #pragma unroll
    for (int o = 16; o; o >>= 1) S += __shfl_xor_sync(0xffffffffu, S, o);
    if (lane == 0) { g_ms[warp * 2] = M; g_ms[warp * 2 + 1] = 1.f / S; }
}

// ---------------- k3: softmax normalize (in place) + gate + fc2 + residual ----
__global__ void __launch_bounds__(256) k3_out(
    const float* __restrict__ feat,
    const float* __restrict__ fc2w, const float* __restrict__ fc2b,
    float* __restrict__ res, float* __restrict__ aout)
{
    extern __shared__ float smd[];
    float* fc2s = smd;            // 128*64
    float* tsm  = smd + 8192;     // 128*128
    __shared__ float msm[DM], rsm[DM], fb[64];

    int tid = threadIdx.x;
    int p0 = blockIdx.x * 128;
    int b = p0 >> 16;             // N_ = 65536

    for (int i = tid * 4; i < 8192; i += 1024)
        *(float4*)(fc2s + i) = *(const float4*)(fc2w + i);
    if (tid < DM) {
        msm[tid] = g_ms[(b * DM + tid) * 2];
        rsm[tid] = g_ms[(b * DM + tid) * 2 + 1];
    }
    if (tid < 64) fb[tid] = fc2b[tid];
    __syncthreads();

    for (int idx = tid; idx < 16384; idx += 256) {
        int c = idx & 127;
        size_t go = (size_t)p0 * DM + idx;
        float a = aout[go];
        float e = __expf(a - msm[c]) * rsm[c];
        aout[go] = e;                     // final attn output
        tsm[idx] = e * g_gv[go];          // gated values
    }
    __syncthreads();

    int tx = tid & 15, ty = tid >> 4;
    int r0 = ty * 8, c0 = tx * 4;
    unsigned long long acc2[8][2];
    #pragma unroll
    for (int i = 0; i < 8; i++) { acc2[i][0] = 0ull; acc2[i][1] = 0ull; }
    #pragma unroll 4
    for (int k = 0; k < DM; k++) {
        ulonglong2 w = *(const ulonglong2*)(fc2s + k * 64 + c0);
        #pragma unroll
        for (int i = 0; i < 8; i++) {
            float a = tsm[(r0 + i) * DM + k];
            unsigned long long aa = pk2(a, a);
            fma2(acc2[i][0], aa, w.x);
            fma2(acc2[i][1], aa, w.y);
        }
    }
    #pragma unroll
    for (int i = 0; i < 8; i++) {
        float v0, v1, v2, v3;
        upk2(acc2[i][0], v0, v1);
        upk2(acc2[i][1], v2, v3);
        size_t ro = (size_t)(p0 + r0 + i) * 64 + c0;
        res[ro + 0] = v0 + fb[c0 + 0] + feat[ro + 0];
        res[ro + 1] = v1 + fb[c0 + 1] + feat[ro + 1];
        res[ro + 2] = v2 + fb[c0 + 2] + feat[ro + 2];
        res[ro + 3] = v3 + fb[c0 + 3] + feat[ro + 3];
    }
}

// ---------------- launch ----------------
extern "C" void kernel_launch(void* const* d_in, const int* in_sizes, int n_in,
                              void* d_out, int out_size)
{
    const float* xyz  = (const float*)d_in[0];
    const float* feat = (const float*)d_in[1];
    const float* fc1w = (const float*)d_in[2];
    const float* fc1b = (const float*)d_in[3];
    const float* fc2w = (const float*)d_in[4];
    const float* fc2b = (const float*)d_in[5];
    const float* d1w  = (const float*)d_in[6];
    const float* d1b  = (const float*)d_in[7];
    const float* d2w  = (const float*)d_in[8];
    const float* d2b  = (const float*)d_in[9];
    const float* g1w  = (const float*)d_in[10];
    const float* g1b  = (const float*)d_in[11];
    const float* g2w  = (const float*)d_in[12];
    const float* g2b  = (const float*)d_in[13];
    const float* wq   = (const float*)d_in[14];
    const float* wk   = (const float*)d_in[15];
    const float* wv   = (const float*)d_in[16];

    float* res  = (float*)d_out;                       // [2,65536,64]
    float* aout = (float*)d_out + (size_t)NPTS * 64;   // [2,65536,128]

    cudaFuncSetAttribute(k1_main, cudaFuncAttributeMaxDynamicSharedMemorySize, 196608);
    cudaFuncSetAttribute(k3_out,  cudaFuncAttributeMaxDynamicSharedMemorySize, 98304);

    k0_fold<<<32, 256>>>(fc1w, fc1b, wq, wk, wv);
    k1_main<<<NPTS / 128, 256, 196608>>>(xyz, feat, d1w, d1b, d2w, d2b,
                                         g1w, g1b, g2w, g2b, aout);
    dim3 g2(DM / 32, NCHUNK, B_), b2(32, 8);
    k2a_stats<<<g2, b2>>>(aout);
    k2b_combine<<<32, 256>>>();
    k3_out<<<NPTS / 128, 256, 98304>>>(feat, fc2w, fc2b, res, aout);
}

// round 9
// speedup vs baseline: 1.5278x; 1.5278x over previous
#include <cuda_runtime.h>
#include <math.h>
#include <cstdint>

#define B_ 2
#define N_ 65536
#define DM 128
#define NPTS (B_*N_)
#define NCHUNK 64
#define SCALE_F 0.088388347648318441f

#if defined(__CUDA_ARCH_FEAT_SM103_ALL) || defined(__CUDA_ARCH_FEAT_SM100_ALL) || defined(__CUDA_ARCH_FEAT_SM101_ALL)
#define HAS_TC 1
#else
#define HAS_TC 0
#endif

// ---------------- device scratch ----------------
__device__ float g_gv[(size_t)NPTS * DM];
__device__ float g_Ws[64 * 128];
__device__ float g_Wv[64 * 128];
__device__ float g_bs[DM];
__device__ float g_bv[DM];
__device__ float g_part[B_ * DM * NCHUNK * 2];
__device__ float g_ms[B_ * DM * 2];
__device__ __align__(128) float g_wimg[131072];
__device__ int g_tc_ok;

#define IMG_D2H 0
#define IMG_D2L 16384
#define IMG_G1H 32768
#define IMG_G1L 49152
#define IMG_G2H 65536
#define IMG_G2L 81920
#define IMG_WSH 98304
#define IMG_WSL 106496
#define IMG_WVH 114688
#define IMG_WVL 122880

// ---------------- generic helpers ----------------
__device__ __forceinline__ uint32_t smem_to_u32(const void* p) {
    uint32_t a;
    asm("{ .reg .u64 t; cvta.to.shared.u64 t, %1; cvt.u32.u64 %0, t; }" : "=r"(a) : "l"(p));
    return a;
}
__device__ __forceinline__ uint32_t cvt_tf32(float x) {
    uint32_t r; asm("cvt.rna.tf32.f32 %0, %1;" : "=r"(r) : "f"(x)); return r;
}
__device__ __forceinline__ void split2(float v, float& hi, float& lo) {
    hi = __uint_as_float(cvt_tf32(v));
    lo = __uint_as_float(cvt_tf32(v - hi));
}
// float index of (row n, col k) in blocked+SW128 operand image (128 rows)
__device__ __forceinline__ int img_off(int n, int k) {
    int in_r = n & 7;
    return (((k >> 5) * 16 + (n >> 3)) << 8) + (in_r << 5)
         + ((((k >> 2) & 7) ^ in_r) << 2) + (k & 3);
}
// packed f32x2
__device__ __forceinline__ unsigned long long pk2(float x, float y) {
    unsigned long long r; asm("mov.b64 %0, {%1, %2};" : "=l"(r) : "f"(x), "f"(y)); return r;
}
__device__ __forceinline__ void fma2(unsigned long long& d, unsigned long long a, unsigned long long b) {
    asm("fma.rn.f32x2 %0, %1, %2, %0;" : "+l"(d) : "l"(a), "l"(b));
}
__device__ __forceinline__ void upk2(unsigned long long v, float& x, float& y) {
    asm("mov.b64 {%0, %1}, %2;" : "=f"(x), "=f"(y) : "l"(v));
}

// ---------------- k0a: fold fc1 into (wq-wk), wv; reset tc flag ------------
__global__ void k0_fold(const float* __restrict__ fc1w, const float* __restrict__ fc1b,
                        const float* __restrict__ wq, const float* __restrict__ wk,
                        const float* __restrict__ wv)
{
    if (blockIdx.x == 0 && threadIdx.x == 0) g_tc_ok = 0;
    int idx = blockIdx.x * 256 + threadIdx.x;
    int m = idx >> 7, j = idx & 127;
    float as = 0.f, av = 0.f;
    for (int k = 0; k < DM; k++) {
        float f = fc1w[m * DM + k];
        as += f * (wq[k * DM + j] - wk[k * DM + j]);
        av += f * wv[k * DM + j];
    }
    g_Ws[idx] = as; g_Wv[idx] = av;
    if (blockIdx.x == 0 && threadIdx.x < DM) {
        int jj = threadIdx.x;
        float bs = 0.f, bv = 0.f;
        for (int k = 0; k < DM; k++) {
            float fb = fc1b[k];
            bs += fb * (wq[k * DM + jj] - wk[k * DM + jj]);
            bv += fb * wv[k * DM + jj];
        }
        g_bs[jj] = bs; g_bv[jj] = bv;
    }
}

// ---------------- k0b: transposed tf32-split swizzled weight images --------
__global__ void k0_img(const float* __restrict__ d2w, const float* __restrict__ g1w,
                       const float* __restrict__ g2w)
{
    int t = blockIdx.x * 256 + threadIdx.x;     // 0..65535
    const float* src; int bh, bl, e;
    if (t < 16384)      { src = d2w;  bh = IMG_D2H; bl = IMG_D2L; e = t; }
    else if (t < 32768) { src = g1w;  bh = IMG_G1H; bl = IMG_G1L; e = t - 16384; }
    else if (t < 49152) { src = g2w;  bh = IMG_G2H; bl = IMG_G2L; e = t - 32768; }
    else if (t < 57344) { src = g_Ws; bh = IMG_WSH; bl = IMG_WSL; e = t - 49152; }
    else                { src = g_Wv; bh = IMG_WVH; bl = IMG_WVL; e = t - 57344; }
    int n = e & 127, k = e >> 7;                // B[n][k] = W[k][n]
    float hi, lo; split2(src[k * 128 + n], hi, lo);
    int off = img_off(n, k);
    g_wimg[bh + off] = hi;
    g_wimg[bl + off] = lo;
}

// ================== tcgen05 path (feature-gated) ==================
#if HAS_TC
__device__ __forceinline__ uint32_t elect_one_pred() {
    uint32_t p;
    asm volatile("{\n\t.reg .pred p;\n\telect.sync _|p, 0xFFFFFFFF;\n\t"
                 "selp.b32 %0, 1, 0, p;\n\t}" : "=r"(p));
    return p;
}
#define TC_ALLOC(sa, n) \
    asm volatile("tcgen05.alloc.cta_group::1.sync.aligned.shared::cta.b32 [%0], %1;" \
                 :: "r"((uint32_t)(sa)), "r"((uint32_t)(n)) : "memory")
#define TC_DEALLOC(t, n) \
    asm volatile("tcgen05.dealloc.cta_group::1.sync.aligned.b32 %0, %1;" :: "r"(t), "r"((uint32_t)(n)))
#define TC_COMMIT(mb) \
    asm volatile("tcgen05.commit.cta_group::1.mbarrier::arrive::one.shared::cluster.b64 [%0];" \
                 :: "r"((uint32_t)(mb)) : "memory")
#define TC_WAIT_LD()  asm volatile("tcgen05.wait::ld.sync.aligned;" ::: "memory")
#define TC_FENCE_BEFORE() asm volatile("tcgen05.fence::before_thread_sync;" ::: "memory")
#define TC_FENCE_AFTER()  asm volatile("tcgen05.fence::after_thread_sync;" ::: "memory")
#define FENCE_ASYNC() asm volatile("fence.proxy.async.shared::cta;" ::: "memory")
#define MB_INIT(mb, c) \
    asm volatile("mbarrier.init.shared.b64 [%0], %1;" :: "r"((uint32_t)(mb)), "r"((uint32_t)(c)) : "memory")
#define MB_WAIT(mb, ph) do { \
    uint32_t _m = (uint32_t)(mb), _p = (uint32_t)(ph), _d; \
    asm volatile("{\n\t.reg .pred p;\n\t" \
        "mbarrier.try_wait.parity.acquire.cta.shared::cta.b64 p, [%1], %2;\n\t" \
        "selp.b32 %0, 1, 0, p;\n\t}" : "=r"(_d) : "r"(_m), "r"(_p) : "memory"); \
    if (!_d) { \
        asm volatile("{\n\t.reg .pred P1;\n\t" \
            "WL_%=:\n\t" \
            "mbarrier.try_wait.parity.acquire.cta.shared::cta.b64 P1, [%0], %1, 0x989680;\n\t" \
            "@P1 bra.uni WD_%=;\n\t" \
            "bra.uni WL_%=;\n\tWD_%=:\n\t}" :: "r"(_m), "r"(_p) : "memory"); \
    } } while (0)
#define LDTM_X32(r, a) \
    asm volatile("tcgen05.ld.sync.aligned.32x32b.x32.b32 " \
        "{%0, %1, %2, %3, %4, %5, %6, %7, %8, %9, %10, %11, %12, %13, %14, %15, " \
        " %16, %17, %18, %19, %20, %21, %22, %23, %24, %25, %26, %27, %28, %29, %30, %31}, [%32];" \
        : "=r"((r)[0]),  "=r"((r)[1]),  "=r"((r)[2]),  "=r"((r)[3]), \
          "=r"((r)[4]),  "=r"((r)[5]),  "=r"((r)[6]),  "=r"((r)[7]), \
          "=r"((r)[8]),  "=r"((r)[9]),  "=r"((r)[10]), "=r"((r)[11]), \
          "=r"((r)[12]), "=r"((r)[13]), "=r"((r)[14]), "=r"((r)[15]), \
          "=r"((r)[16]), "=r"((r)[17]), "=r"((r)[18]), "=r"((r)[19]), \
          "=r"((r)[20]), "=r"((r)[21]), "=r"((r)[22]), "=r"((r)[23]), \
          "=r"((r)[24]), "=r"((r)[25]), "=r"((r)[26]), "=r"((r)[27]), \
          "=r"((r)[28]), "=r"((r)[29]), "=r"((r)[30]), "=r"((r)[31]) \
        : "r"(a))

__device__ __forceinline__ uint64_t make_desc(uint32_t addr) {
    const uint64_t base = (uint64_t(2) << 61) | (uint64_t(1) << 46)
                        | (uint64_t(64) << 32) | (uint64_t(1) << 16);
    return base | ((uint64_t)(addr >> 4) & 0x3FFF);
}
// idesc tf32: dtype F32(1)@4, atype TF32(2)@7, btype TF32(2)@10, N/8@17, M/16@24
#define IDESC_TF32 0x8200910u
__device__ __forceinline__ void mma_tf32(uint32_t d, uint64_t a, uint64_t b, bool en) {
    uint32_t e = en ? 1u : 0u;
    asm volatile("{\n\t.reg .pred p;\n\tsetp.ne.u32 p, %5, 0;\n\t"
        "tcgen05.mma.cta_group::1.kind::tf32 [%0], %1, %2, %3, {%4, %4, %4, %4}, p;\n\t}"
        :: "r"(d), "l"(a), "l"(b), "r"(IDESC_TF32), "r"(0u), "r"(e) : "memory");
}
__device__ __forceinline__ uint64_t koff(int s) {
    return (uint64_t)(((s >> 2) << 10) + ((s & 3) << 1));
}
#endif // HAS_TC

#define K1_SMEM_BYTES 205824
#define TM_P  0
#define TM_D1 128
#define TM_D2 256

__global__ void __launch_bounds__(256, 1) k1_tc(
    const float* __restrict__ xyz, const float* __restrict__ feat,
    const float* __restrict__ d1w, const float* __restrict__ d1b,
    const float* __restrict__ d2b, const float* __restrict__ g1b,
    const float* __restrict__ g2b, float* __restrict__ aout)
{
#if HAS_TC
    extern __shared__ float smraw[];
    uint32_t raw_u = smem_to_u32(smraw);
    uint32_t base_u = (raw_u + 1023u) & ~1023u;
    float* Ah = smraw + ((base_u - raw_u) >> 2);
    float* Al = Ah + 16384;
    float* Wb = Ah + 32768;
    float* aux = Ah + 49152;
    float* d1s = aux;            // 384
    float* xyzs = aux + 384;     // 384
    float* bd1s = aux + 768;     // 128
    float* bsumS = aux + 896;    // 128
    float* bsumV = aux + 1024;   // 128
    float* bg1s = aux + 1152;    // 128
    float* bg2s = aux + 1280;    // 128
    uint32_t* tptr = (uint32_t*)(aux + 1408);
    uint32_t mbar_u = smem_to_u32(aux + 1412);

    const int tid = threadIdx.x;
    const int wid = tid >> 5, lid = tid & 31;
    const int p0 = blockIdx.x * 128;
    const int r  = (wid & 3) * 32 + lid;
    const int cb = (wid >> 2) * 64;
    const uint32_t ah_u = base_u;

    if (blockIdx.x == 0 && tid == 0) g_tc_ok = 1;
    if (wid == 0) TC_ALLOC(smem_to_u32(tptr), 512);
    if (tid == 0) MB_INIT(mbar_u, 1);

    for (int i = tid; i < 384; i += 256) { d1s[i] = d1w[i]; xyzs[i] = xyz[p0 * 3 + i]; }
    if (tid < 128) {
        bd1s[tid]  = d1b[tid];
        bsumS[tid] = g_bs[tid] + d2b[tid];
        bsumV[tid] = g_bv[tid] + d2b[tid];
        bg1s[tid]  = g1b[tid];
        bg2s[tid]  = g2b[tid];
    }
    for (int i = tid * 4; i < 16384; i += 1024)
        *(float4*)(Wb + i) = *(const float4*)(g_wimg + IMG_D2H + i);
    __syncthreads();
    const uint32_t tmem = *tptr;

    const uint64_t dAh = make_desc(ah_u);
    const uint64_t dAl = make_desc(ah_u + 65536);
    const uint64_t dW0 = make_desc(ah_u + 131072);
    const uint64_t dW1 = make_desc(ah_u + 131072 + 32768);

    // hrel = relu(xyz@d1 + bd1) -> split -> Ah/Al
    {
        float x0 = xyzs[r * 3], x1 = xyzs[r * 3 + 1], x2 = xyzs[r * 3 + 2];
        #pragma unroll
        for (int g4 = 0; g4 < 16; g4++) {
            int c0 = cb + g4 * 4;
            float4 h4, l4; float* hp = &h4.x; float* lp = &l4.x;
            #pragma unroll
            for (int j = 0; j < 4; j++) {
                int c = c0 + j;
                float h = fmaxf(x0 * d1s[c] + x1 * d1s[128 + c] + x2 * d1s[256 + c] + bd1s[c], 0.f);
                split2(h, hp[j], lp[j]);
            }
            int fi = img_off(r, c0);
            *(float4*)(Ah + fi) = h4;
            *(float4*)(Al + fi) = l4;
        }
    }
    FENCE_ASYNC(); __syncthreads();

    // phase 0: P = hrelH.d2H + hrelL.d2H
    if (wid == 0 && elect_one_pred()) {
        TC_FENCE_AFTER();
        #pragma unroll
        for (int s = 0; s < 16; s++) mma_tf32(tmem + TM_P, dAh + koff(s), dW0 + koff(s), s > 0);
        #pragma unroll
        for (int s = 0; s < 16; s++) mma_tf32(tmem + TM_P, dAl + koff(s), dW0 + koff(s), true);
        TC_COMMIT(mbar_u);
    }
    MB_WAIT(mbar_u, 0);

    // phase 1: P += hrelH.d2L
    for (int i = tid * 4; i < 16384; i += 1024)
        *(float4*)(Wb + i) = *(const float4*)(g_wimg + IMG_D2L + i);
    FENCE_ASYNC(); __syncthreads();
    if (wid == 0 && elect_one_pred()) {
        TC_FENCE_AFTER();
        #pragma unroll
        for (int s = 0; s < 16; s++) mma_tf32(tmem + TM_P, dAh + koff(s), dW0 + koff(s), true);
        TC_COMMIT(mbar_u);
    }
    MB_WAIT(mbar_u, 1);

    // split feat -> Ah/Al (K=64); load WsH+WsL
    {
        int fcb = (wid >> 2) * 32;
        const float* fr = feat + (size_t)(p0 + r) * 64 + fcb;
        #pragma unroll
        for (int g4 = 0; g4 < 8; g4++) {
            float4 v = *(const float4*)(fr + g4 * 4);
            float4 h4, l4;
            split2(v.x, h4.x, l4.x); split2(v.y, h4.y, l4.y);
            split2(v.z, h4.z, l4.z); split2(v.w, h4.w, l4.w);
            int fi = img_off(r, fcb + g4 * 4);
            *(float4*)(Ah + fi) = h4;
            *(float4*)(Al + fi) = l4;
        }
    }
    for (int i = tid * 4; i < 8192; i += 1024) {
        *(float4*)(Wb + i)        = *(const float4*)(g_wimg + IMG_WSH + i);
        *(float4*)(Wb + 8192 + i) = *(const float4*)(g_wimg + IMG_WSL + i);
    }
    FENCE_ASYNC(); __syncthreads();

    // phase 2: D1 = feat (3xtf32) . Ws
    if (wid == 0 && elect_one_pred()) {
        TC_FENCE_AFTER();
        #pragma unroll
        for (int s = 0; s < 8; s++) mma_tf32(tmem + TM_D1, dAh + koff(s), dW0 + koff(s), s > 0);
        #pragma unroll
        for (int s = 0; s < 8; s++) mma_tf32(tmem + TM_D1, dAl + koff(s), dW0 + koff(s), true);
        #pragma unroll
        for (int s = 0; s < 8; s++) mma_tf32(tmem + TM_D1, dAh + koff(s), dW1 + koff(s), true);
        TC_COMMIT(mbar_u);
    }
    MB_WAIT(mbar_u, 0);

    // phase 3: D2 = feat (3xtf32) . Wv
    for (int i = tid * 4; i < 8192; i += 1024) {
        *(float4*)(Wb + i)        = *(const float4*)(g_wimg + IMG_WVH + i);
        *(float4*)(Wb + 8192 + i) = *(const float4*)(g_wimg + IMG_WVL + i);
    }
    FENCE_ASYNC(); __syncthreads();
    if (wid == 0 && elect_one_pred()) {
        TC_FENCE_AFTER();
        #pragma unroll
        for (int s = 0; s < 8; s++) mma_tf32(tmem + TM_D2, dAh + koff(s), dW0 + koff(s), s > 0);
        #pragma unroll
        for (int s = 0; s < 8; s++) mma_tf32(tmem + TM_D2, dAl + koff(s), dW0 + koff(s), true);
        #pragma unroll
        for (int s = 0; s < 8; s++) mma_tf32(tmem + TM_D2, dAh + koff(s), dW1 + koff(s), true);
        TC_COMMIT(mbar_u);
    }
    MB_WAIT(mbar_u, 1);
    TC_FENCE_AFTER();

    // epilogue: gv = P + D2 + bV -> gmem; S = P + D1 + bS -> split -> Ah/Al
    #pragma unroll
    for (int ch = 0; ch < 2; ch++) {
        int c0 = cb + ch * 32;
        uint32_t pr[32], dr[32];
        LDTM_X32(pr, tmem + TM_P  + c0);
        LDTM_X32(dr, tmem + TM_D2 + c0);
        TC_WAIT_LD();
        float* gvp = g_gv + (size_t)(p0 + r) * 128 + c0;
        #pragma unroll
        for (int g4 = 0; g4 < 8; g4++) {
            float4 o;
            o.x = __uint_as_float(pr[g4*4+0]) + __uint_as_float(dr[g4*4+0]) + bsumV[c0+g4*4+0];
            o.y = __uint_as_float(pr[g4*4+1]) + __uint_as_float(dr[g4*4+1]) + bsumV[c0+g4*4+1];
            o.z = __uint_as_float(pr[g4*4+2]) + __uint_as_float(dr[g4*4+2]) + bsumV[c0+g4*4+2];
            o.w = __uint_as_float(pr[g4*4+3]) + __uint_as_float(dr[g4*4+3]) + bsumV[c0+g4*4+3];
            *(float4*)(gvp + g4 * 4) = o;
        }
        LDTM_X32(dr, tmem + TM_D1 + c0);
        TC_WAIT_LD();
        #pragma unroll
        for (int g4 = 0; g4 < 8; g4++) {
            float4 h4, l4; float* hp = &h4.x; float* lp = &l4.x;
            #pragma unroll
            for (int j = 0; j < 4; j++) {
                float s = __uint_as_float(pr[g4*4+j]) + __uint_as_float(dr[g4*4+j]) + bsumS[c0+g4*4+j];
                split2(s, hp[j], lp[j]);
            }
            int fi = img_off(r, c0 + g4 * 4);
            *(float4*)(Ah + fi) = h4;
            *(float4*)(Al + fi) = l4;
        }
    }
    TC_FENCE_BEFORE();
    for (int i = tid * 4; i < 16384; i += 1024)
        *(float4*)(Wb + i) = *(const float4*)(g_wimg + IMG_G1H + i);
    FENCE_ASYNC(); __syncthreads();

    // phase 4: P = SH.g1H + SL.g1H
    if (wid == 0 && elect_one_pred()) {
        TC_FENCE_AFTER();
        #pragma unroll
        for (int s = 0; s < 16; s++) mma_tf32(tmem + TM_P, dAh + koff(s), dW0 + koff(s), s > 0);
        #pragma unroll
        for (int s = 0; s < 16; s++) mma_tf32(tmem + TM_P, dAl + koff(s), dW0 + koff(s), true);
        TC_COMMIT(mbar_u);
    }
    MB_WAIT(mbar_u, 0);

    // phase 5: P += SH.g1L
    for (int i = tid * 4; i < 16384; i += 1024)
        *(float4*)(Wb + i) = *(const float4*)(g_wimg + IMG_G1L + i);
    FENCE_ASYNC(); __syncthreads();
    if (wid == 0 && elect_one_pred()) {
        TC_FENCE_AFTER();
        #pragma unroll
        for (int s = 0; s < 16; s++) mma_tf32(tmem + TM_P, dAh + koff(s), dW0 + koff(s), true);
        TC_COMMIT(mbar_u);
    }
    MB_WAIT(mbar_u, 1);
    TC_FENCE_AFTER();

    // H = relu(P + bg1) -> split -> Ah/Al
    #pragma unroll
    for (int ch = 0; ch < 2; ch++) {
        int c0 = cb + ch * 32;
        uint32_t pr[32];
        LDTM_X32(pr, tmem + TM_P + c0);
        TC_WAIT_LD();
        #pragma unroll
        for (int g4 = 0; g4 < 8; g4++) {
            float4 h4, l4; float* hp = &h4.x; float* lp = &l4.x;
            #pragma unroll
            for (int j = 0; j < 4; j++) {
                float h = fmaxf(__uint_as_float(pr[g4*4+j]) + bg1s[c0+g4*4+j], 0.f);
                split2(h, hp[j], lp[j]);
            }
            int fi = img_off(r, c0 + g4 * 4);
            *(float4*)(Ah + fi) = h4;
            *(float4*)(Al + fi) = l4;
        }
    }
    TC_FENCE_BEFORE();
    for (int i = tid * 4; i < 16384; i += 1024)
        *(float4*)(Wb + i) = *(const float4*)(g_wimg + IMG_G2H + i);
    FENCE_ASYNC(); __syncthreads();

    // phase 6: D1 = HH.g2H + HL.g2H
    if (wid == 0 && elect_one_pred()) {
        TC_FENCE_AFTER();
        #pragma unroll
        for (int s = 0; s < 16; s++) mma_tf32(tmem + TM_D1, dAh + koff(s), dW0 + koff(s), s > 0);
        #pragma unroll
        for (int s = 0; s < 16; s++) mma_tf32(tmem + TM_D1, dAl + koff(s), dW0 + koff(s), true);
        TC_COMMIT(mbar_u);
    }
    MB_WAIT(mbar_u, 0);

    // phase 7: D1 += HH.g2L
    for (int i = tid * 4; i < 16384; i += 1024)
        *(float4*)(Wb + i) = *(const float4*)(g_wimg + IMG_G2L + i);
    FENCE_ASYNC(); __syncthreads();
    if (wid == 0 && elect_one_pred()) {
        TC_FENCE_AFTER();
        #pragma unroll
        for (int s = 0; s < 16; s++) mma_tf32(tmem + TM_D1, dAh + koff(s), dW0 + koff(s), true);
        TC_COMMIT(mbar_u);
    }
    MB_WAIT(mbar_u, 1);
    TC_FENCE_AFTER();

    // A = (D1 + bg2) * SCALE -> aout
    {
        float* ao = aout + (size_t)(p0 + r) * 128;
        #pragma unroll
        for (int ch = 0; ch < 2; ch++) {
            int c0 = cb + ch * 32;
            uint32_t dr[32];
            LDTM_X32(dr, tmem + TM_D1 + c0);
            TC_WAIT_LD();
            #pragma unroll
            for (int g4 = 0; g4 < 8; g4++) {
                float4 o;
                o.x = (__uint_as_float(dr[g4*4+0]) + bg2s[c0+g4*4+0]) * SCALE_F;
                o.y = (__uint_as_float(dr[g4*4+1]) + bg2s[c0+g4*4+1]) * SCALE_F;
                o.z = (__uint_as_float(dr[g4*4+2]) + bg2s[c0+g4*4+2]) * SCALE_F;
                o.w = (__uint_as_float(dr[g4*4+3]) + bg2s[c0+g4*4+3]) * SCALE_F;
                *(float4*)(ao + c0 + g4 * 4) = o;
            }
        }
    }
    TC_FENCE_BEFORE();
    __syncthreads();
    if (wid == 0) TC_DEALLOC(tmem, 512);
#endif // HAS_TC
}

// ================== FFMA2 fallback (runs only if tc path didn't) ==========
__device__ __forceinline__ void gemm_tile2(const float* __restrict__ A, int lda,
                                           const float* __restrict__ W, int ldw, int K,
                                           int r0, int c0, float acc[8][8])
{
    unsigned long long acc2[8][4];
    #pragma unroll
    for (int i = 0; i < 8; i++)
        #pragma unroll
        for (int j = 0; j < 4; j++) acc2[i][j] = 0ull;
    #pragma unroll 2
    for (int k = 0; k < K; k += 2) {
        ulonglong2 w00 = *(const ulonglong2*)(W + (size_t)k * ldw + c0);
        ulonglong2 w01 = *(const ulonglong2*)(W + (size_t)k * ldw + c0 + 4);
        ulonglong2 w10 = *(const ulonglong2*)(W + (size_t)(k + 1) * ldw + c0);
        ulonglong2 w11 = *(const ulonglong2*)(W + (size_t)(k + 1) * ldw + c0 + 4);
        #pragma unroll
        for (int i = 0; i < 8; i++) {
            float2 a2 = *(const float2*)(A + (r0 + i) * lda + k);
            unsigned long long a0 = pk2(a2.x, a2.x);
            unsigned long long a1 = pk2(a2.y, a2.y);
            fma2(acc2[i][0], a0, w00.x); fma2(acc2[i][1], a0, w00.y);
            fma2(acc2[i][2], a0, w01.x); fma2(acc2[i][3], a0, w01.y);
            fma2(acc2[i][0], a1, w10.x); fma2(acc2[i][1], a1, w10.y);
            fma2(acc2[i][2], a1, w11.x); fma2(acc2[i][3], a1, w11.y);
        }
    }
    #pragma unroll
    for (int i = 0; i < 8; i++)
        #pragma unroll
        for (int j = 0; j < 4; j++)
            upk2(acc2[i][j], acc[i][2 * j], acc[i][2 * j + 1]);
}

__global__ void __launch_bounds__(256) k1_fb(
    const float* __restrict__ xyz, const float* __restrict__ feat,
    const float* __restrict__ d1w, const float* __restrict__ d1b,
    const float* __restrict__ d2w, const float* __restrict__ d2b,
    const float* __restrict__ g1w, const float* __restrict__ g1b,
    const float* __restrict__ g2w, const float* __restrict__ g2b,
    float* __restrict__ aout)
{
    if (g_tc_ok) return;   // tc path already produced aout/g_gv

    extern __shared__ float smd[];
    float* Wsm = smd;
    float* Pm  = smd + 16384;
    float* Tm  = smd + 32768;
    __shared__ float d1s[384], xyzs[384];
    __shared__ float bd1[DM], bd2[DM], bg1[DM], bg2[DM], bss[DM], bvv[DM];

    const int tid = threadIdx.x;
    const int tx = tid & 15, ty = tid >> 4;
    const int r0 = ty * 8, c0 = tx * 8;
    const int p0 = blockIdx.x * 128;

    for (int i = tid; i < 384; i += 256) { d1s[i] = d1w[i]; xyzs[i] = xyz[p0 * 3 + i]; }
    if (tid < DM) {
        bd1[tid] = d1b[tid]; bd2[tid] = d2b[tid];
        bg1[tid] = g1b[tid]; bg2[tid] = g2b[tid];
        bss[tid] = g_bs[tid]; bvv[tid] = g_bv[tid];
    }
    for (int i = tid * 4; i < 16384; i += 1024)
        *(float4*)(Wsm + i) = *(const float4*)(d2w + i);
    __syncthreads();

    #pragma unroll
    for (int i = 0; i < 8; i++) {
        int p = r0 + i;
        float x0 = xyzs[p * 3], x1 = xyzs[p * 3 + 1], x2 = xyzs[p * 3 + 2];
        #pragma unroll
        for (int j = 0; j < 8; j++) {
            int c = c0 + j;
            float h = x0 * d1s[c] + x1 * d1s[DM + c] + x2 * d1s[2 * DM + c] + bd1[c];
            Tm[p * DM + c] = fmaxf(h, 0.f);
        }
    }
    __syncthreads();

    float acc[8][8];
    gemm_tile2(Tm, DM, Wsm, DM, DM, r0, c0, acc);
    #pragma unroll
    for (int i = 0; i < 8; i++)
        #pragma unroll
        for (int j = 0; j < 8; j++)
            Pm[(r0 + i) * DM + c0 + j] = acc[i][j] + bd2[c0 + j];
    __syncthreads();

    for (int i = tid * 4; i < 8192; i += 1024) {
        *(float4*)(Tm + i)  = *(const float4*)(feat + p0 * 64 + i);
        *(float4*)(Wsm + i) = *(const float4*)(g_Wv + i);
    }
    __syncthreads();

    gemm_tile2(Tm, 64, Wsm, DM, 64, r0, c0, acc);
    #pragma unroll
    for (int i = 0; i < 8; i++)
        #pragma unroll
        for (int j = 0; j < 8; j++)
            g_gv[(size_t)(p0 + r0 + i) * DM + c0 + j] =
                acc[i][j] + bvv[c0 + j] + Pm[(r0 + i) * DM + c0 + j];
    __syncthreads();

    for (int i = tid * 4; i < 8192; i += 1024)
        *(float4*)(Wsm + i) = *(const float4*)(g_Ws + i);
    __syncthreads();

    gemm_tile2(Tm, 64, Wsm, DM, 64, r0, c0, acc);
    #pragma unroll
    for (int i = 0; i < 8; i++)
        #pragma unroll
        for (int j = 0; j < 8; j++) {
            int o = (r0 + i) * DM + c0 + j;
            Pm[o] = acc[i][j] + bss[c0 + j] + Pm[o];
        }
    __syncthreads();

    for (int i = tid * 4; i < 16384; i += 1024)
        *(float4*)(Wsm + i) = *(const float4*)(g1w + i);
    __syncthreads();

    gemm_tile2(Pm, DM, Wsm, DM, DM, r0, c0, acc);
    #pragma unroll
    for (int i = 0; i < 8; i++)
        #pragma unroll
        for (int j = 0; j < 8; j++)
            Tm[(r0 + i) * DM + c0 + j] = fmaxf(acc[i][j] + bg1[c0 + j], 0.f);
    __syncthreads();

    for (int i = tid * 4; i < 16384; i += 1024)
        *(float4*)(Wsm + i) = *(const float4*)(g2w + i);
    __syncthreads();

    gemm_tile2(Tm, DM, Wsm, DM, DM, r0, c0, acc);
    #pragma unroll
    for (int i = 0; i < 8; i++)
        #pragma unroll
        for (int j = 0; j < 8; j++)
            aout[(size_t)(p0 + r0 + i) * DM + c0 + j] =
                (acc[i][j] + bg2[c0 + j]) * SCALE_F;
}

// ---------------- k2a: per-chunk online (max,sum) over N ----------------
__global__ void k2a_stats(const float* __restrict__ aout)
{
    int tx = threadIdx.x, ty = threadIdx.y;
    int c = blockIdx.x * 32 + tx;
    int chunk = blockIdx.y, b = blockIdx.z;
    const float* base = aout + (size_t)b * N_ * DM + c;
    const int rows = N_ / NCHUNK;
    int n0 = chunk * rows;

    float m = -3.4e38f, s = 0.f;
    #pragma unroll 4
    for (int n = n0 + ty; n < n0 + rows; n += 8) {
        float a = base[(size_t)n * DM];
        float nm = fmaxf(m, a);
        s = s * __expf(m - nm) + __expf(a - nm);
        m = nm;
    }
    __shared__ float smm[8][32], sms[8][32];
    smm[ty][tx] = m; sms[ty][tx] = s;
    __syncthreads();
    if (ty == 0) {
        float M = m, S = s;
        #pragma unroll
        for (int rr = 1; rr < 8; rr++) {
            float m2 = smm[rr][tx], s2 = sms[rr][tx];
            float nM = fmaxf(M, m2);
            S = S * __expf(M - nM) + s2 * __expf(m2 - nM);
            M = nM;
        }
        int o = ((b * DM + c) * NCHUNK + chunk) * 2;
        g_part[o] = M; g_part[o + 1] = S;
    }
}

// ---------------- k2b: combine chunk partials ----------------
__global__ void k2b_combine()
{
    int warp = (blockIdx.x * blockDim.x + threadIdx.x) >> 5;
    int lane = threadIdx.x & 31;
    const float* p = g_part + (size_t)warp * NCHUNK * 2;
    float m1 = p[lane * 2],        s1 = p[lane * 2 + 1];
    float m2 = p[(lane + 32) * 2], s2 = p[(lane + 32) * 2 + 1];
    float M = fmaxf(m1, m2);
    #pragma unroll
    for (int o = 16; o; o >>= 1) M = fmaxf(M, __shfl_xor_sync(0xffffffffu, M, o));
    float S = s1 * __expf(m1 - M) + s2 * __expf(m2 - M);
    #pragma unroll
    for (int o = 16; o; o >>= 1) S += __shfl_xor_sync(0xffffffffu, S, o);
    if (lane == 0) { g_ms[warp * 2] = M; g_ms[warp * 2 + 1] = 1.f / S; }
}

// ---------------- k3: normalize + gate + fc2 + residual ----------------
__global__ void __launch_bounds__(256) k3_out(
    const float* __restrict__ feat,
    const float* __restrict__ fc2w, const float* __restrict__ fc2b,
    float* __restrict__ res, float* __restrict__ aout)
{
    extern __shared__ float smd[];
    float* fc2s = smd;
    float* tsm  = smd + 8192;
    __shared__ float msm[DM], rsm[DM], fb[64];

    int tid = threadIdx.x;
    int p0 = blockIdx.x * 128;
    int b = p0 >> 16;

    for (int i = tid * 4; i < 8192; i += 1024)
        *(float4*)(fc2s + i) = *(const float4*)(fc2w + i);
    if (tid < DM) {
        msm[tid] = g_ms[(b * DM + tid) * 2];
        rsm[tid] = g_ms[(b * DM + tid) * 2 + 1];
    }
    if (tid < 64) fb[tid] = fc2b[tid];
    __syncthreads();

    for (int idx = tid; idx < 16384; idx += 256) {
        int c = idx & 127;
        size_t go = (size_t)p0 * DM + idx;
        float a = aout[go];
        float e = __expf(a - msm[c]) * rsm[c];
        aout[go] = e;
        tsm[idx] = e * g_gv[go];
    }
    __syncthreads();

    int tx = tid & 15, ty = tid >> 4;
    int r0 = ty * 8, c0 = tx * 4;
    unsigned long long acc2[8][2];
    #pragma unroll
    for (int i = 0; i < 8; i++) { acc2[i][0] = 0ull; acc2[i][1] = 0ull; }
    #pragma unroll 4
    for (int k = 0; k < DM; k++) {
        ulonglong2 w = *(const ulonglong2*)(fc2s + k * 64 + c0);
        #pragma unroll
        for (int i = 0; i < 8; i++) {
            float a = tsm[(r0 + i) * DM + k];
            unsigned long long aa = pk2(a, a);
            fma2(acc2[i][0], aa, w.x);
            fma2(acc2[i][1], aa, w.y);
        }
    }
    #pragma unroll
    for (int i = 0; i < 8; i++) {
        float v0, v1, v2, v3;
        upk2(acc2[i][0], v0, v1);
        upk2(acc2[i][1], v2, v3);
        size_t ro = (size_t)(p0 + r0 + i) * 64 + c0;
        res[ro + 0] = v0 + fb[c0 + 0] + feat[ro + 0];
        res[ro + 1] = v1 + fb[c0 + 1] + feat[ro + 1];
        res[ro + 2] = v2 + fb[c0 + 2] + feat[ro + 2];
        res[ro + 3] = v3 + fb[c0 + 3] + feat[ro + 3];
    }
}

// ---------------- launch ----------------
extern "C" void kernel_launch(void* const* d_in, const int* in_sizes, int n_in,
                              void* d_out, int out_size)
{
    const float* xyz  = (const float*)d_in[0];
    const float* feat = (const float*)d_in[1];
    const float* fc1w = (const float*)d_in[2];
    const float* fc1b = (const float*)d_in[3];
    const float* fc2w = (const float*)d_in[4];
    const float* fc2b = (const float*)d_in[5];
    const float* d1w  = (const float*)d_in[6];
    const float* d1b  = (const float*)d_in[7];
    const float* d2w  = (const float*)d_in[8];
    const float* d2b  = (const float*)d_in[9];
    const float* g1w  = (const float*)d_in[10];
    const float* g1b  = (const float*)d_in[11];
    const float* g2w  = (const float*)d_in[12];
    const float* g2b  = (const float*)d_in[13];
    const float* wq   = (const float*)d_in[14];
    const float* wk   = (const float*)d_in[15];
    const float* wv   = (const float*)d_in[16];

    float* res  = (float*)d_out;
    float* aout = (float*)d_out + (size_t)NPTS * 64;

    cudaFuncSetAttribute(k1_tc, cudaFuncAttributeMaxDynamicSharedMemorySize, K1_SMEM_BYTES);
    cudaFuncSetAttribute(k1_fb, cudaFuncAttributeMaxDynamicSharedMemorySize, 196608);
    cudaFuncSetAttribute(k3_out, cudaFuncAttributeMaxDynamicSharedMemorySize, 98304);

    k0_fold<<<32, 256>>>(fc1w, fc1b, wq, wk, wv);
    k0_img<<<256, 256>>>(d2w, g1w, g2w);
    k1_tc<<<NPTS / 128, 256, K1_SMEM_BYTES>>>(xyz, feat, d1w, d1b, d2b, g1b, g2b, aout);
    k1_fb<<<NPTS / 128, 256, 196608>>>(xyz, feat, d1w, d1b, d2w, d2b,
                                       g1w, g1b, g2w, g2b, aout);
    dim3 g2(DM / 32, NCHUNK, B_), b2(32, 8);
    k2a_stats<<<g2, b2>>>(aout);
    k2b_combine<<<32, 256>>>();
    k3_out<<<NPTS / 128, 256, 98304>>>(feat, fc2w, fc2b, res, aout);
}

// round 10
// speedup vs baseline: 2.2218x; 1.4542x over previous
#include <cuda_runtime.h>
#include <cuda_bf16.h>
#include <math.h>
#include <cstdint>

#define B_ 2
#define N_ 65536
#define DM 128
#define NPTS (B_*N_)
#define SCALE_F 0.088388347648318441f
#define NPART 512   /* CTAs per batch in k1 */

#if defined(__CUDA_ARCH_FEAT_SM103_ALL) || defined(__CUDA_ARCH_FEAT_SM100_ALL) || defined(__CUDA_ARCH_FEAT_SM101_ALL)
#define HAS_TC 1
#else
#define HAS_TC 0
#endif

// ---------------- device scratch ----------------
__device__ float g_gv[(size_t)NPTS * DM];
__device__ float g_Ws[64 * 128];
__device__ float g_Wv[64 * 128];
__device__ float g_bs[DM];
__device__ float g_bv[DM];
__device__ float g_part[B_ * DM * NPART * 2];
__device__ float g_ms[B_ * DM * 2];
__device__ __align__(128) unsigned char g_wimg[262144];  // bf16 hi/lo weight images
__device__ int g_tc_ok;

// byte offsets into g_wimg
#define IW_D2H 0
#define IW_D2L 32768
#define IW_G1H 65536
#define IW_G1L 98304
#define IW_G2H 131072
#define IW_G2L 163840
#define IW_WSH 196608   /* WsL contiguous at +16384 */
#define IW_WVH 229376   /* WvL contiguous at +16384 */

// ---------------- generic helpers ----------------
__device__ __forceinline__ uint32_t smem_to_u32(const void* p) {
    uint32_t a;
    asm("{ .reg .u64 t; cvta.to.shared.u64 t, %1; cvt.u32.u64 %0, t; }" : "=r"(a) : "l"(p));
    return a;
}
// byte offset of (row n, col k) in blocked+SW128 bf16 operand image (128 rows)
__device__ __forceinline__ int img2_off(int n, int k) {
    int a = (((k >> 6) * 16 + (n >> 3)) << 10) + ((n & 7) << 7) + ((k & 63) << 1);
    return a ^ ((a >> 3) & 0x70);
}
__device__ __forceinline__ void splitbf(float v, float& hi, float& lo) {
    hi = __bfloat162float(__float2bfloat16_rn(v));
    lo = v - hi;
}
__device__ __forceinline__ uint32_t pkbf(float lo, float hi) {
    uint32_t r;
    asm("cvt.rn.bf16x2.f32 %0, %1, %2;" : "=r"(r) : "f"(hi), "f"(lo));
    return r;
}
__device__ __forceinline__ uint4 pk8(const float* f) {
    uint4 u;
    u.x = pkbf(f[0], f[1]); u.y = pkbf(f[2], f[3]);
    u.z = pkbf(f[4], f[5]); u.w = pkbf(f[6], f[7]);
    return u;
}
// packed f32x2 (k3 / fallback)
__device__ __forceinline__ unsigned long long pk2(float x, float y) {
    unsigned long long r; asm("mov.b64 %0, {%1, %2};" : "=l"(r) : "f"(x), "f"(y)); return r;
}
__device__ __forceinline__ void fma2(unsigned long long& d, unsigned long long a, unsigned long long b) {
    asm("fma.rn.f32x2 %0, %1, %2, %0;" : "+l"(d) : "l"(a), "l"(b));
}
__device__ __forceinline__ void upk2(unsigned long long v, float& x, float& y) {
    asm("mov.b64 {%0, %1}, %2;" : "=f"(x), "=f"(y) : "l"(v));
}

// ---------------- k0a: fold fc1 into (wq-wk), wv; reset tc flag ------------
__global__ void k0_fold(const float* __restrict__ fc1w, const float* __restrict__ fc1b,
                        const float* __restrict__ wq, const float* __restrict__ wk,
                        const float* __restrict__ wv)
{
    if (blockIdx.x == 0 && threadIdx.x == 0) g_tc_ok = 0;
    int idx = blockIdx.x * 256 + threadIdx.x;
    int m = idx >> 7, j = idx & 127;
    float as = 0.f, av = 0.f;
    for (int k = 0; k < DM; k++) {
        float f = fc1w[m * DM + k];
        as += f * (wq[k * DM + j] - wk[k * DM + j]);
        av += f * wv[k * DM + j];
    }
    g_Ws[idx] = as; g_Wv[idx] = av;
    if (blockIdx.x == 0 && threadIdx.x < DM) {
        int jj = threadIdx.x;
        float bs = 0.f, bv = 0.f;
        for (int k = 0; k < DM; k++) {
            float fb = fc1b[k];
            bs += fb * (wq[k * DM + jj] - wk[k * DM + jj]);
            bv += fb * wv[k * DM + jj];
        }
        g_bs[jj] = bs; g_bv[jj] = bv;
    }
}

// ---------------- k0b: transposed bf16-split swizzled weight images --------
__global__ void k0_img(const float* __restrict__ d2w, const float* __restrict__ g1w,
                       const float* __restrict__ g2w)
{
    int t = blockIdx.x * 256 + threadIdx.x;     // 0..65535
    const float* src; int bh, bl, e;
    if (t < 16384)      { src = d2w;  bh = IW_D2H; bl = IW_D2L;        e = t; }
    else if (t < 32768) { src = g1w;  bh = IW_G1H; bl = IW_G1L;        e = t - 16384; }
    else if (t < 49152) { src = g2w;  bh = IW_G2H; bl = IW_G2L;        e = t - 32768; }
    else if (t < 57344) { src = g_Ws; bh = IW_WSH; bl = IW_WSH + 16384; e = t - 49152; }
    else                { src = g_Wv; bh = IW_WVH; bl = IW_WVH + 16384; e = t - 57344; }
    int n = e & 127, k = e >> 7;                // B[n][k] = W[k][n]
    float w = src[k * 128 + n];
    __nv_bfloat16 hb = __float2bfloat16_rn(w);
    __nv_bfloat16 lb = __float2bfloat16_rn(w - __bfloat162float(hb));
    int off = img2_off(n, k);
    *(__nv_bfloat16*)(g_wimg + bh + off) = hb;
    *(__nv_bfloat16*)(g_wimg + bl + off) = lb;
}

// ================== tcgen05 path (feature-gated) ==================
#if HAS_TC
__device__ __forceinline__ uint32_t elect_one_pred() {
    uint32_t p;
    asm volatile("{\n\t.reg .pred p;\n\telect.sync _|p, 0xFFFFFFFF;\n\t"
                 "selp.b32 %0, 1, 0, p;\n\t}" : "=r"(p));
    return p;
}
#define TC_ALLOC(sa, n) \
    asm volatile("tcgen05.alloc.cta_group::1.sync.aligned.shared::cta.b32 [%0], %1;" \
                 :: "r"((uint32_t)(sa)), "r"((uint32_t)(n)) : "memory")
#define TC_RELINQ() \
    asm volatile("tcgen05.relinquish_alloc_permit.cta_group::1.sync.aligned;")
#define TC_DEALLOC(t, n) \
    asm volatile("tcgen05.dealloc.cta_group::1.sync.aligned.b32 %0, %1;" :: "r"(t), "r"((uint32_t)(n)))
#define TC_COMMIT(mb) \
    asm volatile("tcgen05.commit.cta_group::1.mbarrier::arrive::one.shared::cluster.b64 [%0];" \
                 :: "r"((uint32_t)(mb)) : "memory")
#define TC_WAIT_LD()  asm volatile("tcgen05.wait::ld.sync.aligned;" ::: "memory")
#define TC_FENCE_BEFORE() asm volatile("tcgen05.fence::before_thread_sync;" ::: "memory")
#define TC_FENCE_AFTER()  asm volatile("tcgen05.fence::after_thread_sync;" ::: "memory")
#define FENCE_ASYNC() asm volatile("fence.proxy.async.shared::cta;" ::: "memory")
#define MB_INIT(mb, c) \
    asm volatile("mbarrier.init.shared.b64 [%0], %1;" :: "r"((uint32_t)(mb)), "r"((uint32_t)(c)) : "memory")
#define MB_WAIT(mb, ph) do { \
    uint32_t _m = (uint32_t)(mb), _p = (uint32_t)(ph), _d; \
    asm volatile("{\n\t.reg .pred p;\n\t" \
        "mbarrier.try_wait.parity.acquire.cta.shared::cta.b64 p, [%1], %2;\n\t" \
        "selp.b32 %0, 1, 0, p;\n\t}" : "=r"(_d) : "r"(_m), "r"(_p) : "memory"); \
    if (!_d) { \
        asm volatile("{\n\t.reg .pred P1;\n\t" \
            "WL_%=:\n\t" \
            "mbarrier.try_wait.parity.acquire.cta.shared::cta.b64 P1, [%0], %1, 0x989680;\n\t" \
            "@P1 bra.uni WD_%=;\n\t" \
            "bra.uni WL_%=;\n\tWD_%=:\n\t}" :: "r"(_m), "r"(_p) : "memory"); \
    } } while (0)
#define LDTM_X32(r, a) \
    asm volatile("tcgen05.ld.sync.aligned.32x32b.x32.b32 " \
        "{%0, %1, %2, %3, %4, %5, %6, %7, %8, %9, %10, %11, %12, %13, %14, %15, " \
        " %16, %17, %18, %19, %20, %21, %22, %23, %24, %25, %26, %27, %28, %29, %30, %31}, [%32];" \
        : "=r"((r)[0]),  "=r"((r)[1]),  "=r"((r)[2]),  "=r"((r)[3]), \
          "=r"((r)[4]),  "=r"((r)[5]),  "=r"((r)[6]),  "=r"((r)[7]), \
          "=r"((r)[8]),  "=r"((r)[9]),  "=r"((r)[10]), "=r"((r)[11]), \
          "=r"((r)[12]), "=r"((r)[13]), "=r"((r)[14]), "=r"((r)[15]), \
          "=r"((r)[16]), "=r"((r)[17]), "=r"((r)[18]), "=r"((r)[19]), \
          "=r"((r)[20]), "=r"((r)[21]), "=r"((r)[22]), "=r"((r)[23]), \
          "=r"((r)[24]), "=r"((r)[25]), "=r"((r)[26]), "=r"((r)[27]), \
          "=r"((r)[28]), "=r"((r)[29]), "=r"((r)[30]), "=r"((r)[31]) \
        : "r"(a))

__device__ __forceinline__ uint64_t make_desc(uint32_t addr) {
    const uint64_t base = (uint64_t(2) << 61) | (uint64_t(1) << 46)
                        | (uint64_t(64) << 32) | (uint64_t(1) << 16);
    return base | ((uint64_t)(addr >> 4) & 0x3FFF);
}
// bf16 idesc: dtype F32(1)@4, atype BF16(1)@7, btype BF16(1)@10, N/8@17, M/16@24
#define IDESC_BF16 0x8200490u
__device__ __forceinline__ void mma_bf(uint32_t d, uint64_t a, uint64_t b, bool en) {
    uint32_t e = en ? 1u : 0u;
    asm volatile("{\n\t.reg .pred p;\n\tsetp.ne.u32 p, %5, 0;\n\t"
        "tcgen05.mma.cta_group::1.kind::f16 [%0], %1, %2, %3, {%4, %4, %4, %4}, p;\n\t}"
        :: "r"(d), "l"(a), "l"(b), "r"(IDESC_BF16), "r"(0u), "r"(e) : "memory");
}
// K-step s: 16 bf16 = 32 B = 2 units; atom-col per 4 steps, stride 1024 units
__device__ __forceinline__ uint64_t koff(int s) {
    return (uint64_t)(((s >> 2) << 10) + ((s & 3) << 1));
}
#endif // HAS_TC

#define K1_SMEM_BYTES 109072
#define TM_P  0
#define TM_D  128

__global__ void __launch_bounds__(256, 2) k1_tc(
    const float* __restrict__ xyz, const float* __restrict__ feat,
    const float* __restrict__ d1w, const float* __restrict__ d1b,
    const float* __restrict__ d2b, const float* __restrict__ g1b,
    const float* __restrict__ g2b, float* __restrict__ aout)
{
#if HAS_TC
    extern __shared__ char smraw[];
    uint32_t raw_u = smem_to_u32(smraw);
    uint32_t base_u = (raw_u + 1023u) & ~1023u;
    char* base = smraw + (base_u - raw_u);
    char* AhB = base;
    char* AlB = base + 32768;
    char* WbB = base + 65536;
    float* aux = (float*)(base + 98304);
    float* d1s   = aux;           // 384
    float* xyzs  = aux + 384;     // 384
    float* bd1s  = aux + 768;     // 128
    float* bsumS = aux + 896;     // 128
    float* bsumV = aux + 1024;    // 128
    float* bg1s  = aux + 1152;    // 128
    float* bg2s  = aux + 1280;    // 128
    float* part  = aux + 1408;    // 8*64*2 = 1024
    uint32_t* tptr = (uint32_t*)(aux + 2432);
    uint32_t mbar_u = smem_to_u32(aux + 2434);

    const int tid = threadIdx.x;
    const int wid = tid >> 5, lid = tid & 31;
    const int p0 = blockIdx.x * 128;
    const int r  = (wid & 3) * 32 + lid;     // owned row / TMEM lane
    const int cb = (wid >> 2) * 64;          // k / channel half [cb, cb+64)

    if (blockIdx.x == 0 && tid == 0) g_tc_ok = 1;
    if (wid == 0) { TC_ALLOC(smem_to_u32(tptr), 256); TC_RELINQ(); }
    if (tid == 0) MB_INIT(mbar_u, 1);

    for (int i = tid; i < 384; i += 256) { d1s[i] = d1w[i]; xyzs[i] = xyz[p0 * 3 + i]; }
    if (tid < 128) {
        bd1s[tid]  = d1b[tid];
        bsumS[tid] = g_bs[tid] + d2b[tid];
        bsumV[tid] = g_bv[tid] + d2b[tid];
        bg1s[tid]  = g1b[tid];
        bg2s[tid]  = g2b[tid];
    }
    for (int i = tid * 16; i < 32768; i += 4096)
        *(uint4*)(WbB + i) = *(const uint4*)(g_wimg + IW_D2H + i);
    __syncthreads();
    const uint32_t tmem = *tptr;
    const uint32_t ah_u = base_u;
    const uint64_t dAh = make_desc(ah_u);
    const uint64_t dAl = make_desc(ah_u + 32768);
    const uint64_t dW0 = make_desc(ah_u + 65536);
    const uint64_t dW1 = make_desc(ah_u + 65536 + 16384);

    // hrel = relu(xyz@d1 + bd1) -> bf16 split -> Ah/Al (K=128 image)
    {
        float x0 = xyzs[r * 3], x1 = xyzs[r * 3 + 1], x2 = xyzs[r * 3 + 2];
        #pragma unroll
        for (int g8 = 0; g8 < 8; g8++) {
            int k0 = cb + g8 * 8;
            float h8[8], l8[8];
            #pragma unroll
            for (int j = 0; j < 8; j++) {
                int c = k0 + j;
                float h = fmaxf(x0 * d1s[c] + x1 * d1s[128 + c] + x2 * d1s[256 + c] + bd1s[c], 0.f);
                splitbf(h, h8[j], l8[j]);
            }
            int off = img2_off(r, k0);
            *(uint4*)(AhB + off) = pk8(h8);
            *(uint4*)(AlB + off) = pk8(l8);
        }
    }
    FENCE_ASYNC(); __syncthreads();

    // R1: P = hrelH.d2H + hrelL.d2H
    if (wid == 0 && elect_one_pred()) {
        TC_FENCE_AFTER();
        #pragma unroll
        for (int s = 0; s < 8; s++) mma_bf(tmem + TM_P, dAh + koff(s), dW0 + koff(s), s > 0);
        #pragma unroll
        for (int s = 0; s < 8; s++) mma_bf(tmem + TM_P, dAl + koff(s), dW0 + koff(s), true);
        TC_COMMIT(mbar_u);
    }
    MB_WAIT(mbar_u, 0);

    // R2: P += hrelH.d2L
    for (int i = tid * 16; i < 32768; i += 4096)
        *(uint4*)(WbB + i) = *(const uint4*)(g_wimg + IW_D2L + i);
    FENCE_ASYNC(); __syncthreads();
    if (wid == 0 && elect_one_pred()) {
        TC_FENCE_AFTER();
        #pragma unroll
        for (int s = 0; s < 8; s++) mma_bf(tmem + TM_P, dAh + koff(s), dW0 + koff(s), true);
        TC_COMMIT(mbar_u);
    }
    MB_WAIT(mbar_u, 1);

    // feat -> bf16 split -> Ah/Al (K=64); load WvH+WvL (contiguous 32KB)
    {
        int fcb = (wid >> 2) * 32;
        const float* fr = feat + (size_t)(p0 + r) * 64 + fcb;
        #pragma unroll
        for (int g8 = 0; g8 < 4; g8++) {
            float4 v0 = *(const float4*)(fr + g8 * 8);
            float4 v1 = *(const float4*)(fr + g8 * 8 + 4);
            float h8[8], l8[8];
            splitbf(v0.x, h8[0], l8[0]); splitbf(v0.y, h8[1], l8[1]);
            splitbf(v0.z, h8[2], l8[2]); splitbf(v0.w, h8[3], l8[3]);
            splitbf(v1.x, h8[4], l8[4]); splitbf(v1.y, h8[5], l8[5]);
            splitbf(v1.z, h8[6], l8[6]); splitbf(v1.w, h8[7], l8[7]);
            int off = img2_off(r, fcb + g8 * 8);
            *(uint4*)(AhB + off) = pk8(h8);
            *(uint4*)(AlB + off) = pk8(l8);
        }
    }
    for (int i = tid * 16; i < 32768; i += 4096)
        *(uint4*)(WbB + i) = *(const uint4*)(g_wimg + IW_WVH + i);
    FENCE_ASYNC(); __syncthreads();

    // R3: D = feat(3 terms).Wv
    if (wid == 0 && elect_one_pred()) {
        TC_FENCE_AFTER();
        #pragma unroll
        for (int s = 0; s < 4; s++) mma_bf(tmem + TM_D, dAh + koff(s), dW0 + koff(s), s > 0);
        #pragma unroll
        for (int s = 0; s < 4; s++) mma_bf(tmem + TM_D, dAl + koff(s), dW0 + koff(s), true);
        #pragma unroll
        for (int s = 0; s < 4; s++) mma_bf(tmem + TM_D, dAh + koff(s), dW1 + koff(s), true);
        TC_COMMIT(mbar_u);
    }
    MB_WAIT(mbar_u, 0);
    TC_FENCE_AFTER();

    // load Ws (overwrites Wv; MMAs done) + gv epilogue: gv = P + D + bV
    for (int i = tid * 16; i < 32768; i += 4096)
        *(uint4*)(WbB + i) = *(const uint4*)(g_wimg + IW_WSH + i);
    #pragma unroll
    for (int ch = 0; ch < 2; ch++) {
        int c0 = cb + ch * 32;
        uint32_t pr[32], dr[32];
        LDTM_X32(pr, tmem + TM_P + c0);
        LDTM_X32(dr, tmem + TM_D + c0);
        TC_WAIT_LD();
        float* gvp = g_gv + (size_t)(p0 + r) * 128 + c0;
        #pragma unroll
        for (int g4 = 0; g4 < 8; g4++) {
            float4 o;
            o.x = __uint_as_float(pr[g4*4+0]) + __uint_as_float(dr[g4*4+0]) + bsumV[c0+g4*4+0];
            o.y = __uint_as_float(pr[g4*4+1]) + __uint_as_float(dr[g4*4+1]) + bsumV[c0+g4*4+1];
            o.z = __uint_as_float(pr[g4*4+2]) + __uint_as_float(dr[g4*4+2]) + bsumV[c0+g4*4+2];
            o.w = __uint_as_float(pr[g4*4+3]) + __uint_as_float(dr[g4*4+3]) + bsumV[c0+g4*4+3];
            *(float4*)(gvp + g4 * 4) = o;
        }
    }
    TC_FENCE_BEFORE(); FENCE_ASYNC(); __syncthreads();

    // R4: D = feat(3 terms).Ws  (overwrite)
    if (wid == 0 && elect_one_pred()) {
        TC_FENCE_AFTER();
        #pragma unroll
        for (int s = 0; s < 4; s++) mma_bf(tmem + TM_D, dAh + koff(s), dW0 + koff(s), s > 0);
        #pragma unroll
        for (int s = 0; s < 4; s++) mma_bf(tmem + TM_D, dAl + koff(s), dW0 + koff(s), true);
        #pragma unroll
        for (int s = 0; s < 4; s++) mma_bf(tmem + TM_D, dAh + koff(s), dW1 + koff(s), true);
        TC_COMMIT(mbar_u);
    }
    MB_WAIT(mbar_u, 1);
    TC_FENCE_AFTER();

    // load g1H + S epilogue: S = P + D + bS -> split -> Ah/Al
    for (int i = tid * 16; i < 32768; i += 4096)
        *(uint4*)(WbB + i) = *(const uint4*)(g_wimg + IW_G1H + i);
    #pragma unroll
    for (int ch = 0; ch < 2; ch++) {
        int c0 = cb + ch * 32;
        uint32_t pr[32], dr[32];
        LDTM_X32(pr, tmem + TM_P + c0);
        LDTM_X32(dr, tmem + TM_D + c0);
        TC_WAIT_LD();
        #pragma unroll
        for (int g8 = 0; g8 < 4; g8++) {
            float h8[8], l8[8];
            #pragma unroll
            for (int j = 0; j < 8; j++) {
                int jj = g8 * 8 + j;
                float s = __uint_as_float(pr[jj]) + __uint_as_float(dr[jj]) + bsumS[c0 + jj];
                splitbf(s, h8[j], l8[j]);
            }
            int off = img2_off(r, c0 + g8 * 8);
            *(uint4*)(AhB + off) = pk8(h8);
            *(uint4*)(AlB + off) = pk8(l8);
        }
    }
    TC_FENCE_BEFORE(); FENCE_ASYNC(); __syncthreads();

    // R5: P = SH.g1H + SL.g1H (overwrite)
    if (wid == 0 && elect_one_pred()) {
        TC_FENCE_AFTER();
        #pragma unroll
        for (int s = 0; s < 8; s++) mma_bf(tmem + TM_P, dAh + koff(s), dW0 + koff(s), s > 0);
        #pragma unroll
        for (int s = 0; s < 8; s++) mma_bf(tmem + TM_P, dAl + koff(s), dW0 + koff(s), true);
        TC_COMMIT(mbar_u);
    }
    MB_WAIT(mbar_u, 0);

    // R6: P += SH.g1L
    for (int i = tid * 16; i < 32768; i += 4096)
        *(uint4*)(WbB + i) = *(const uint4*)(g_wimg + IW_G1L + i);
    FENCE_ASYNC(); __syncthreads();
    if (wid == 0 && elect_one_pred()) {
        TC_FENCE_AFTER();
        #pragma unroll
        for (int s = 0; s < 8; s++) mma_bf(tmem + TM_P, dAh + koff(s), dW0 + koff(s), true);
        TC_COMMIT(mbar_u);
    }
    MB_WAIT(mbar_u, 1);
    TC_FENCE_AFTER();

    // load g2H + H epilogue: H = relu(P + bg1) -> split -> Ah/Al
    for (int i = tid * 16; i < 32768; i += 4096)
        *(uint4*)(WbB + i) = *(const uint4*)(g_wimg + IW_G2H + i);
    #pragma unroll
    for (int ch = 0; ch < 2; ch++) {
        int c0 = cb + ch * 32;
        uint32_t pr[32];
        LDTM_X32(pr, tmem + TM_P + c0);
        TC_WAIT_LD();
        #pragma unroll
        for (int g8 = 0; g8 < 4; g8++) {
            float h8[8], l8[8];
            #pragma unroll
            for (int j = 0; j < 8; j++) {
                int jj = g8 * 8 + j;
                float h = fmaxf(__uint_as_float(pr[jj]) + bg1s[c0 + jj], 0.f);
                splitbf(h, h8[j], l8[j]);
            }
            int off = img2_off(r, c0 + g8 * 8);
            *(uint4*)(AhB + off) = pk8(h8);
            *(uint4*)(AlB + off) = pk8(l8);
        }
    }
    TC_FENCE_BEFORE(); FENCE_ASYNC(); __syncthreads();

    // R7: D = HH.g2H + HL.g2H (overwrite)
    if (wid == 0 && elect_one_pred()) {
        TC_FENCE_AFTER();
        #pragma unroll
        for (int s = 0; s < 8; s++) mma_bf(tmem + TM_D, dAh + koff(s), dW0 + koff(s), s > 0);
        #pragma unroll
        for (int s = 0; s < 8; s++) mma_bf(tmem + TM_D, dAl + koff(s), dW0 + koff(s), true);
        TC_COMMIT(mbar_u);
    }
    MB_WAIT(mbar_u, 0);

    // R8: D += HH.g2L
    for (int i = tid * 16; i < 32768; i += 4096)
        *(uint4*)(WbB + i) = *(const uint4*)(g_wimg + IW_G2L + i);
    FENCE_ASYNC(); __syncthreads();
    if (wid == 0 && elect_one_pred()) {
        TC_FENCE_AFTER();
        #pragma unroll
        for (int s = 0; s < 8; s++) mma_bf(tmem + TM_D, dAh + koff(s), dW0 + koff(s), true);
        TC_COMMIT(mbar_u);
    }
    MB_WAIT(mbar_u, 1);
    TC_FENCE_AFTER();

    // A epilogue: logits -> aout, + per-CTA softmax partials (max, sumexp)
    {
        float* ao = aout + (size_t)(p0 + r) * 128;
        #pragma unroll
        for (int ch = 0; ch < 2; ch++) {
            int c0 = cb + ch * 32;
            uint32_t dr[32];
            LDTM_X32(dr, tmem + TM_D + c0);
            TC_WAIT_LD();
            #pragma unroll
            for (int j = 0; j < 32; j++)
                dr[j] = __float_as_uint((__uint_as_float(dr[j]) + bg2s[c0 + j]) * SCALE_F);
            #pragma unroll
            for (int g4 = 0; g4 < 8; g4++) {
                float4 o;
                o.x = __uint_as_float(dr[g4*4+0]); o.y = __uint_as_float(dr[g4*4+1]);
                o.z = __uint_as_float(dr[g4*4+2]); o.w = __uint_as_float(dr[g4*4+3]);
                *(float4*)(ao + c0 + g4 * 4) = o;
            }
            // per-channel (rows = lanes) reduction
            #pragma unroll
            for (int j = 0; j < 32; j++) {
                float v = __uint_as_float(dr[j]);
                float m = v;
                #pragma unroll
                for (int o = 16; o; o >>= 1) m = fmaxf(m, __shfl_xor_sync(0xffffffffu, m, o));
                float e = __expf(v - m);
                #pragma unroll
                for (int o = 16; o; o >>= 1) e += __shfl_xor_sync(0xffffffffu, e, o);
                if (lid == 0) {
                    part[wid * 128 + (ch * 32 + j) * 2]     = m;
                    part[wid * 128 + (ch * 32 + j) * 2 + 1] = e;
                }
            }
        }
    }
    TC_FENCE_BEFORE();
    __syncthreads();
    if (wid == 0) TC_DEALLOC(tmem, 256);

    // combine 4 warps per channel -> g_part
    if (tid < 128) {
        int c = tid, grp = c >> 6, lc = c & 63;
        float M = -3.4e38f, S = 0.f;
        #pragma unroll
        for (int w = 0; w < 4; w++) {
            int wd = grp * 4 + w;
            float m2 = part[wd * 128 + lc * 2], s2 = part[wd * 128 + lc * 2 + 1];
            float nM = fmaxf(M, m2);
            S = S * __expf(M - nM) + s2 * __expf(m2 - nM);
            M = nM;
        }
        int b = blockIdx.x >> 9, cl = blockIdx.x & 511;
        int o = ((b * 128 + c) * NPART + cl) * 2;
        g_part[o] = M; g_part[o + 1] = S;
    }
#endif // HAS_TC
}

// ================== FFMA2 fallback path (runs only if tc path didn't) ======
__device__ __forceinline__ void gemm_tile2(const float* __restrict__ A, int lda,
                                           const float* __restrict__ W, int ldw, int K,
                                           int r0, int c0, float acc[8][8])
{
    unsigned long long acc2[8][4];
    #pragma unroll
    for (int i = 0; i < 8; i++)
        #pragma unroll
        for (int j = 0; j < 4; j++) acc2[i][j] = 0ull;
    #pragma unroll 2
    for (int k = 0; k < K; k += 2) {
        ulonglong2 w00 = *(const ulonglong2*)(W + (size_t)k * ldw + c0);
        ulonglong2 w01 = *(const ulonglong2*)(W + (size_t)k * ldw + c0 + 4);
        ulonglong2 w10 = *(const ulonglong2*)(W + (size_t)(k + 1) * ldw + c0);
        ulonglong2 w11 = *(const ulonglong2*)(W + (size_t)(k + 1) * ldw + c0 + 4);
        #pragma unroll
        for (int i = 0; i < 8; i++) {
            float2 a2 = *(const float2*)(A + (r0 + i) * lda + k);
            unsigned long long a0 = pk2(a2.x, a2.x);
            unsigned long long a1 = pk2(a2.y, a2.y);
            fma2(acc2[i][0], a0, w00.x); fma2(acc2[i][1], a0, w00.y);
            fma2(acc2[i][2], a0, w01.x); fma2(acc2[i][3], a0, w01.y);
            fma2(acc2[i][0], a1, w10.x); fma2(acc2[i][1], a1, w10.y);
            fma2(acc2[i][2], a1, w11.x); fma2(acc2[i][3], a1, w11.y);
        }
    }
    #pragma unroll
    for (int i = 0; i < 8; i++)
        #pragma unroll
        for (int j = 0; j < 4; j++)
            upk2(acc2[i][j], acc[i][2 * j], acc[i][2 * j + 1]);
}

__global__ void __launch_bounds__(256) k1_fb(
    const float* __restrict__ xyz, const float* __restrict__ feat,
    const float* __restrict__ d1w, const float* __restrict__ d1b,
    const float* __restrict__ d2w, const float* __restrict__ d2b,
    const float* __restrict__ g1w, const float* __restrict__ g1b,
    const float* __restrict__ g2w, const float* __restrict__ g2b,
    float* __restrict__ aout)
{
    if (g_tc_ok) return;

    extern __shared__ float smd[];
    float* Wsm = smd;
    float* Pm  = smd + 16384;
    float* Tm  = smd + 32768;
    __shared__ float d1s[384], xyzs[384];
    __shared__ float bd1[DM], bd2[DM], bg1[DM], bg2[DM], bss[DM], bvv[DM];

    const int tid = threadIdx.x;
    const int tx = tid & 15, ty = tid >> 4;
    const int r0 = ty * 8, c0 = tx * 8;
    const int p0 = blockIdx.x * 128;

    for (int i = tid; i < 384; i += 256) { d1s[i] = d1w[i]; xyzs[i] = xyz[p0 * 3 + i]; }
    if (tid < DM) {
        bd1[tid] = d1b[tid]; bd2[tid] = d2b[tid];
        bg1[tid] = g1b[tid]; bg2[tid] = g2b[tid];
        bss[tid] = g_bs[tid]; bvv[tid] = g_bv[tid];
    }
    for (int i = tid * 4; i < 16384; i += 1024)
        *(float4*)(Wsm + i) = *(const float4*)(d2w + i);
    __syncthreads();

    #pragma unroll
    for (int i = 0; i < 8; i++) {
        int p = r0 + i;
        float x0 = xyzs[p * 3], x1 = xyzs[p * 3 + 1], x2 = xyzs[p * 3 + 2];
        #pragma unroll
        for (int j = 0; j < 8; j++) {
            int c = c0 + j;
            float h = x0 * d1s[c] + x1 * d1s[DM + c] + x2 * d1s[2 * DM + c] + bd1[c];
            Tm[p * DM + c] = fmaxf(h, 0.f);
        }
    }
    __syncthreads();

    float acc[8][8];
    gemm_tile2(Tm, DM, Wsm, DM, DM, r0, c0, acc);
    #pragma unroll
    for (int i = 0; i < 8; i++)
        #pragma unroll
        for (int j = 0; j < 8; j++)
            Pm[(r0 + i) * DM + c0 + j] = acc[i][j] + bd2[c0 + j];
    __syncthreads();

    for (int i = tid * 4; i < 8192; i += 1024) {
        *(float4*)(Tm + i)  = *(const float4*)(feat + p0 * 64 + i);
        *(float4*)(Wsm + i) = *(const float4*)(g_Wv + i);
    }
    __syncthreads();

    gemm_tile2(Tm, 64, Wsm, DM, 64, r0, c0, acc);
    #pragma unroll
    for (int i = 0; i < 8; i++)
        #pragma unroll
        for (int j = 0; j < 8; j++)
            g_gv[(size_t)(p0 + r0 + i) * DM + c0 + j] =
                acc[i][j] + bvv[c0 + j] + Pm[(r0 + i) * DM + c0 + j];
    __syncthreads();

    for (int i = tid * 4; i < 8192; i += 1024)
        *(float4*)(Wsm + i) = *(const float4*)(g_Ws + i);
    __syncthreads();

    gemm_tile2(Tm, 64, Wsm, DM, 64, r0, c0, acc);
    #pragma unroll
    for (int i = 0; i < 8; i++)
        #pragma unroll
        for (int j = 0; j < 8; j++) {
            int o = (r0 + i) * DM + c0 + j;
            Pm[o] = acc[i][j] + bss[c0 + j] + Pm[o];
        }
    __syncthreads();

    for (int i = tid * 4; i < 16384; i += 1024)
        *(float4*)(Wsm + i) = *(const float4*)(g1w + i);
    __syncthreads();

    gemm_tile2(Pm, DM, Wsm, DM, DM, r0, c0, acc);
    #pragma unroll
    for (int i = 0; i < 8; i++)
        #pragma unroll
        for (int j = 0; j < 8; j++)
            Tm[(r0 + i) * DM + c0 + j] = fmaxf(acc[i][j] + bg1[c0 + j], 0.f);
    __syncthreads();

    for (int i = tid * 4; i < 16384; i += 1024)
        *(float4*)(Wsm + i) = *(const float4*)(g2w + i);
    __syncthreads();

    gemm_tile2(Tm, DM, Wsm, DM, DM, r0, c0, acc);
    #pragma unroll
    for (int i = 0; i < 8; i++)
        #pragma unroll
        for (int j = 0; j < 8; j++)
            aout[(size_t)(p0 + r0 + i) * DM + c0 + j] =
                (acc[i][j] + bg2[c0 + j]) * SCALE_F;
}

// fallback stats: per-128-row-block partials (skipped when tc path ran)
__global__ void k2a_fb(const float* __restrict__ aout)
{
    if (g_tc_ok) return;
    int cl = blockIdx.x, b = blockIdx.y;
    int tid = threadIdx.x;
    int c = tid & 127, half = tid >> 7;
    const float* base = aout + ((size_t)(b * N_ + cl * 128 + half * 64)) * 128 + c;
    float m = -3.4e38f, s = 0.f;
    #pragma unroll 4
    for (int rr = 0; rr < 64; rr++) {
        float a = base[(size_t)rr * 128];
        float nm = fmaxf(m, a);
        s = s * __expf(m - nm) + __expf(a - nm);
        m = nm;
    }
    __shared__ float sm[256][2];
    sm[tid][0] = m; sm[tid][1] = s;
    __syncthreads();
    if (half == 0) {
        float m2 = sm[tid + 128][0], s2 = sm[tid + 128][1];
        float nM = fmaxf(m, m2);
        float S = s * __expf(m - nM) + s2 * __expf(m2 - nM);
        int o = ((b * 128 + c) * NPART + cl) * 2;
        g_part[o] = nM; g_part[o + 1] = S;
    }
}

// ---------------- k2b: combine NPART partials per (b,c) ----------------
__global__ void k2b_combine()
{
    int warp = (blockIdx.x * blockDim.x + threadIdx.x) >> 5;  // 0..255
    int lane = threadIdx.x & 31;
    const float* p = g_part + (size_t)warp * NPART * 2;
    float M = -3.4e38f, S = 0.f;
    for (int j = lane; j < NPART; j += 32) {
        float m2 = p[j * 2], s2 = p[j * 2 + 1];
        float nM = fmaxf(M, m2);
        S = S * __expf(M - nM) + s2 * __expf(m2 - nM);
        M = nM;
    }
    #pragma unroll
    for (int o = 16; o; o >>= 1) {
        float m2 = __shfl_xor_sync(0xffffffffu, M, o);
        float s2 = __shfl_xor_sync(0xffffffffu, S, o);
        float nM = fmaxf(M, m2);
        S = S * __expf(M - nM) + s2 * __expf(m2 - nM);
        M = nM;
    }
    if (lane == 0) { g_ms[warp * 2] = M; g_ms[warp * 2 + 1] = 1.f / S; }
}

// ---------------- k3: normalize + gate + fc2 + residual ----------------
__global__ void __launch_bounds__(256) k3_out(
    const float* __restrict__ feat,
    const float* __restrict__ fc2w, const float* __restrict__ fc2b,
    float* __restrict__ res, float* __restrict__ aout)
{
    extern __shared__ float smd[];
    float* fc2s = smd;
    float* tsm  = smd + 8192;
    __shared__ float msm[DM], rsm[DM], fb[64];

    int tid = threadIdx.x;
    int p0 = blockIdx.x * 128;
    int b = p0 >> 16;

    for (int i = tid * 4; i < 8192; i += 1024)
        *(float4*)(fc2s + i) = *(const float4*)(fc2w + i);
    if (tid < DM) {
        msm[tid] = g_ms[(b * DM + tid) * 2];
        rsm[tid] = g_ms[(b * DM + tid) * 2 + 1];
    }
    if (tid < 64) fb[tid] = fc2b[tid];
    __syncthreads();

    for (int idx = tid; idx < 16384; idx += 256) {
        int c = idx & 127;
        size_t go = (size_t)p0 * DM + idx;
        float a = aout[go];
        float e = __expf(a - msm[c]) * rsm[c];
        aout[go] = e;
        tsm[idx] = e * g_gv[go];
    }
    __syncthreads();

    int tx = tid & 15, ty = tid >> 4;
    int r0 = ty * 8, c0 = tx * 4;
    unsigned long long acc2[8][2];
    #pragma unroll
    for (int i = 0; i < 8; i++) { acc2[i][0] = 0ull; acc2[i][1] = 0ull; }
    #pragma unroll 4
    for (int k = 0; k < DM; k++) {
        ulonglong2 w = *(const ulonglong2*)(fc2s + k * 64 + c0);
        #pragma unroll
        for (int i = 0; i < 8; i++) {
            float a = tsm[(r0 + i) * DM + k];
            unsigned long long aa = pk2(a, a);
            fma2(acc2[i][0], aa, w.x);
            fma2(acc2[i][1], aa, w.y);
        }
    }
    #pragma unroll
    for (int i = 0; i < 8; i++) {
        float v0, v1, v2, v3;
        upk2(acc2[i][0], v0, v1);
        upk2(acc2[i][1], v2, v3);
        size_t ro = (size_t)(p0 + r0 + i) * 64 + c0;
        res[ro + 0] = v0 + fb[c0 + 0] + feat[ro + 0];
        res[ro + 1] = v1 + fb[c0 + 1] + feat[ro + 1];
        res[ro + 2] = v2 + fb[c0 + 2] + feat[ro + 2];
        res[ro + 3] = v3 + fb[c0 + 3] + feat[ro + 3];
    }
}

// ---------------- launch ----------------
extern "C" void kernel_launch(void* const* d_in, const int* in_sizes, int n_in,
                              void* d_out, int out_size)
{
    const float* xyz  = (const float*)d_in[0];
    const float* feat = (const float*)d_in[1];
    const float* fc1w = (const float*)d_in[2];
    const float* fc1b = (const float*)d_in[3];
    const float* fc2w = (const float*)d_in[4];
    const float* fc2b = (const float*)d_in[5];
    const float* d1w  = (const float*)d_in[6];
    const float* d1b  = (const float*)d_in[7];
    const float* d2w  = (const float*)d_in[8];
    const float* d2b  = (const float*)d_in[9];
    const float* g1w  = (const float*)d_in[10];
    const float* g1b  = (const float*)d_in[11];
    const float* g2w  = (const float*)d_in[12];
    const float* g2b  = (const float*)d_in[13];
    const float* wq   = (const float*)d_in[14];
    const float* wk   = (const float*)d_in[15];
    const float* wv   = (const float*)d_in[16];

    float* res  = (float*)d_out;
    float* aout = (float*)d_out + (size_t)NPTS * 64;

    cudaFuncSetAttribute(k1_tc, cudaFuncAttributeMaxDynamicSharedMemorySize, K1_SMEM_BYTES);
    cudaFuncSetAttribute(k1_fb, cudaFuncAttributeMaxDynamicSharedMemorySize, 196608);
    cudaFuncSetAttribute(k3_out, cudaFuncAttributeMaxDynamicSharedMemorySize, 98304);

    k0_fold<<<32, 256>>>(fc1w, fc1b, wq, wk, wv);
    k0_img<<<256, 256>>>(d2w, g1w, g2w);
    k1_tc<<<NPTS / 128, 256, K1_SMEM_BYTES>>>(xyz, feat, d1w, d1b, d2b, g1b, g2b, aout);
    k1_fb<<<NPTS / 128, 256, 196608>>>(xyz, feat, d1w, d1b, d2w, d2b,
                                       g1w, g1b, g2w, g2b, aout);
    dim3 gfb(NPART, B_);
    k2a_fb<<<gfb, 256>>>(aout);
    k2b_combine<<<32, 256>>>();
    k3_out<<<NPTS / 128, 256, 98304>>>(feat, fc2w, fc2b, res, aout);
}

// round 11
// speedup vs baseline: 2.2220x; 1.0001x over previous
#include <cuda_runtime.h>
#include <cuda_bf16.h>
#include <math.h>
#include <cstdint>

#define B_ 2
#define N_ 65536
#define DM 128
#define NPTS (B_*N_)
#define SCALE_F 0.088388347648318441f
#define NPART 512

#if defined(__CUDA_ARCH_FEAT_SM103_ALL) || defined(__CUDA_ARCH_FEAT_SM100_ALL) || defined(__CUDA_ARCH_FEAT_SM101_ALL)
#define HAS_TC 1
#else
#define HAS_TC 0
#endif

// ---------------- device scratch ----------------
__device__ float g_gv[(size_t)NPTS * DM];
__device__ float g_Ws[64 * 128];
__device__ float g_Wv[64 * 128];
__device__ float g_bs[DM];
__device__ float g_bv[DM];
__device__ float g_part[B_ * DM * NPART * 2];
__device__ float g_ms[B_ * DM * 2];
__device__ __align__(128) unsigned char g_wimg[294912];  // bf16 hi/lo weight images
__device__ int g_tc_ok;

#define IW_D2H 0
#define IW_D2L 32768
#define IW_G1H 65536
#define IW_G1L 98304
#define IW_G2H 131072
#define IW_G2L 163840
#define IW_WSH 196608   /* lo at +16384 */
#define IW_WVH 229376   /* lo at +16384 */
#define IW_FCH 262144   /* fc2 (N=64 layout), lo at +16384 */

// ---------------- generic helpers ----------------
__device__ __forceinline__ uint32_t smem_to_u32(const void* p) {
    uint32_t a;
    asm("{ .reg .u64 t; cvta.to.shared.u64 t, %1; cvt.u32.u64 %0, t; }" : "=r"(a) : "l"(p));
    return a;
}
// (row n, col k) byte offset in blocked+SW128 bf16 image, 128 rows
__device__ __forceinline__ int img2_off(int n, int k) {
    int a = (((k >> 6) * 16 + (n >> 3)) << 10) + ((n & 7) << 7) + ((k & 63) << 1);
    return a ^ ((a >> 3) & 0x70);
}
// same, 64 rows (N=64 B operand): 8 atoms per 64-col k-block
__device__ __forceinline__ int img64_off(int n, int k) {
    int a = (((k >> 6) * 8 + (n >> 3)) << 10) + ((n & 7) << 7) + ((k & 63) << 1);
    return a ^ ((a >> 3) & 0x70);
}
__device__ __forceinline__ void splitbf(float v, float& hi, float& lo) {
    hi = __bfloat162float(__float2bfloat16_rn(v));
    lo = v - hi;
}
__device__ __forceinline__ uint32_t pkbf(float lo, float hi) {
    uint32_t r;
    asm("cvt.rn.bf16x2.f32 %0, %1, %2;" : "=r"(r) : "f"(hi), "f"(lo));
    return r;
}
__device__ __forceinline__ uint4 pk8(const float* f) {
    uint4 u;
    u.x = pkbf(f[0], f[1]); u.y = pkbf(f[2], f[3]);
    u.z = pkbf(f[4], f[5]); u.w = pkbf(f[6], f[7]);
    return u;
}
__device__ __forceinline__ unsigned long long pk2(float x, float y) {
    unsigned long long r; asm("mov.b64 %0, {%1, %2};" : "=l"(r) : "f"(x), "f"(y)); return r;
}
__device__ __forceinline__ void fma2(unsigned long long& d, unsigned long long a, unsigned long long b) {
    asm("fma.rn.f32x2 %0, %1, %2, %0;" : "+l"(d) : "l"(a), "l"(b));
}
__device__ __forceinline__ void upk2(unsigned long long v, float& x, float& y) {
    asm("mov.b64 {%0, %1}, %2;" : "=f"(x), "=f"(y) : "l"(v));
}

// ---------------- k0a ----------------
__global__ void k0_fold(const float* __restrict__ fc1w, const float* __restrict__ fc1b,
                        const float* __restrict__ wq, const float* __restrict__ wk,
                        const float* __restrict__ wv)
{
    if (blockIdx.x == 0 && threadIdx.x == 0) g_tc_ok = 0;
    int idx = blockIdx.x * 256 + threadIdx.x;
    int m = idx >> 7, j = idx & 127;
    float as = 0.f, av = 0.f;
    for (int k = 0; k < DM; k++) {
        float f = fc1w[m * DM + k];
        as += f * (wq[k * DM + j] - wk[k * DM + j]);
        av += f * wv[k * DM + j];
    }
    g_Ws[idx] = as; g_Wv[idx] = av;
    if (blockIdx.x == 0 && threadIdx.x < DM) {
        int jj = threadIdx.x;
        float bs = 0.f, bv = 0.f;
        for (int k = 0; k < DM; k++) {
            float fb = fc1b[k];
            bs += fb * (wq[k * DM + jj] - wk[k * DM + jj]);
            bv += fb * wv[k * DM + jj];
        }
        g_bs[jj] = bs; g_bv[jj] = bv;
    }
}

// ---------------- k0b: weight images ----------------
__global__ void k0_img(const float* __restrict__ d2w, const float* __restrict__ g1w,
                       const float* __restrict__ g2w, const float* __restrict__ fc2w)
{
    int t = blockIdx.x * 256 + threadIdx.x;     // 0..73727
    if (t >= 73728) return;
    const float* src; int bh, bl, e;
    if (t < 16384)      { src = d2w;  bh = IW_D2H; bl = IW_D2L;         e = t; }
    else if (t < 32768) { src = g1w;  bh = IW_G1H; bl = IW_G1L;         e = t - 16384; }
    else if (t < 49152) { src = g2w;  bh = IW_G2H; bl = IW_G2L;         e = t - 32768; }
    else if (t < 57344) { src = g_Ws; bh = IW_WSH; bl = IW_WSH + 16384; e = t - 49152; }
    else if (t < 65536) { src = g_Wv; bh = IW_WVH; bl = IW_WVH + 16384; e = t - 57344; }
    else {
        // fc2: [128,64] -> B[n][k] = fc2w[k*64+n], 64-row image
        e = t - 65536;
        int n = e & 63, k = e >> 6;
        float w = fc2w[k * 64 + n];
        __nv_bfloat16 hb = __float2bfloat16_rn(w);
        __nv_bfloat16 lb = __float2bfloat16_rn(w - __bfloat162float(hb));
        int off = img64_off(n, k);
        *(__nv_bfloat16*)(g_wimg + IW_FCH + off) = hb;
        *(__nv_bfloat16*)(g_wimg + IW_FCH + 16384 + off) = lb;
        return;
    }
    int n = e & 127, k = e >> 7;
    float w = src[k * 128 + n];
    __nv_bfloat16 hb = __float2bfloat16_rn(w);
    __nv_bfloat16 lb = __float2bfloat16_rn(w - __bfloat162float(hb));
    int off = img2_off(n, k);
    *(__nv_bfloat16*)(g_wimg + bh + off) = hb;
    *(__nv_bfloat16*)(g_wimg + bl + off) = lb;
}

// ================== tcgen05 machinery ==================
#if HAS_TC
__device__ __forceinline__ uint32_t elect_one_pred() {
    uint32_t p;
    asm volatile("{\n\t.reg .pred p;\n\telect.sync _|p, 0xFFFFFFFF;\n\t"
                 "selp.b32 %0, 1, 0, p;\n\t}" : "=r"(p));
    return p;
}
#define TC_ALLOC(sa, n) \
    asm volatile("tcgen05.alloc.cta_group::1.sync.aligned.shared::cta.b32 [%0], %1;" \
                 :: "r"((uint32_t)(sa)), "r"((uint32_t)(n)) : "memory")
#define TC_RELINQ() \
    asm volatile("tcgen05.relinquish_alloc_permit.cta_group::1.sync.aligned;")
#define TC_DEALLOC(t, n) \
    asm volatile("tcgen05.dealloc.cta_group::1.sync.aligned.b32 %0, %1;" :: "r"(t), "r"((uint32_t)(n)))
#define TC_COMMIT(mb) \
    asm volatile("tcgen05.commit.cta_group::1.mbarrier::arrive::one.shared::cluster.b64 [%0];" \
                 :: "r"((uint32_t)(mb)) : "memory")
#define TC_WAIT_LD()  asm volatile("tcgen05.wait::ld.sync.aligned;" ::: "memory")
#define TC_FENCE_BEFORE() asm volatile("tcgen05.fence::before_thread_sync;" ::: "memory")
#define TC_FENCE_AFTER()  asm volatile("tcgen05.fence::after_thread_sync;" ::: "memory")
#define FENCE_ASYNC() asm volatile("fence.proxy.async.shared::cta;" ::: "memory")
#define MB_INIT(mb, c) \
    asm volatile("mbarrier.init.shared.b64 [%0], %1;" :: "r"((uint32_t)(mb)), "r"((uint32_t)(c)) : "memory")
#define MB_WAIT(mb, ph) do { \
    uint32_t _m = (uint32_t)(mb), _p = (uint32_t)(ph), _d; \
    asm volatile("{\n\t.reg .pred p;\n\t" \
        "mbarrier.try_wait.parity.acquire.cta.shared::cta.b64 p, [%1], %2;\n\t" \
        "selp.b32 %0, 1, 0, p;\n\t}" : "=r"(_d) : "r"(_m), "r"(_p) : "memory"); \
    if (!_d) { \
        asm volatile("{\n\t.reg .pred P1;\n\t" \
            "WL_%=:\n\t" \
            "mbarrier.try_wait.parity.acquire.cta.shared::cta.b64 P1, [%0], %1, 0x989680;\n\t" \
            "@P1 bra.uni WD_%=;\n\t" \
            "bra.uni WL_%=;\n\tWD_%=:\n\t}" :: "r"(_m), "r"(_p) : "memory"); \
    } } while (0)
#define LDTM_X32(r, a) \
    asm volatile("tcgen05.ld.sync.aligned.32x32b.x32.b32 " \
        "{%0, %1, %2, %3, %4, %5, %6, %7, %8, %9, %10, %11, %12, %13, %14, %15, " \
        " %16, %17, %18, %19, %20, %21, %22, %23, %24, %25, %26, %27, %28, %29, %30, %31}, [%32];" \
        : "=r"((r)[0]),  "=r"((r)[1]),  "=r"((r)[2]),  "=r"((r)[3]), \
          "=r"((r)[4]),  "=r"((r)[5]),  "=r"((r)[6]),  "=r"((r)[7]), \
          "=r"((r)[8]),  "=r"((r)[9]),  "=r"((r)[10]), "=r"((r)[11]), \
          "=r"((r)[12]), "=r"((r)[13]), "=r"((r)[14]), "=r"((r)[15]), \
          "=r"((r)[16]), "=r"((r)[17]), "=r"((r)[18]), "=r"((r)[19]), \
          "=r"((r)[20]), "=r"((r)[21]), "=r"((r)[22]), "=r"((r)[23]), \
          "=r"((r)[24]), "=r"((r)[25]), "=r"((r)[26]), "=r"((r)[27]), \
          "=r"((r)[28]), "=r"((r)[29]), "=r"((r)[30]), "=r"((r)[31]) \
        : "r"(a))

__device__ __forceinline__ uint64_t make_desc(uint32_t addr) {
    const uint64_t base = (uint64_t(2) << 61) | (uint64_t(1) << 46)
                        | (uint64_t(64) << 32) | (uint64_t(1) << 16);
    return base | ((uint64_t)(addr >> 4) & 0x3FFF);
}
#define IDESC_BF16   0x8200490u   /* M=128, N=128 */
#define IDESC_BF16_64 0x8100490u  /* M=128, N=64  */
__device__ __forceinline__ void mma_bf(uint32_t d, uint64_t a, uint64_t b, uint32_t idesc, bool en) {
    uint32_t e = en ? 1u : 0u;
    asm volatile("{\n\t.reg .pred p;\n\tsetp.ne.u32 p, %5, 0;\n\t"
        "tcgen05.mma.cta_group::1.kind::f16 [%0], %1, %2, %3, {%4, %4, %4, %4}, p;\n\t}"
        :: "r"(d), "l"(a), "l"(b), "r"(idesc), "r"(0u), "r"(e) : "memory");
}
__device__ __forceinline__ uint64_t koff(int s)   { return (uint64_t)(((s >> 2) << 10) + ((s & 3) << 1)); }
__device__ __forceinline__ uint64_t koff64(int s) { return (uint64_t)(((s >> 2) << 9)  + ((s & 3) << 1)); }
#endif // HAS_TC

#define K1_SMEM_BYTES 109072
#define TM_P  0
#define TM_D  128

__global__ void __launch_bounds__(256, 2) k1_tc(
    const float* __restrict__ xyz, const float* __restrict__ feat,
    const float* __restrict__ d1w, const float* __restrict__ d1b,
    const float* __restrict__ d2b, const float* __restrict__ g1b,
    const float* __restrict__ g2b, float* __restrict__ aout)
{
#if HAS_TC
    extern __shared__ char smraw[];
    uint32_t raw_u = smem_to_u32(smraw);
    uint32_t base_u = (raw_u + 1023u) & ~1023u;
    char* base = smraw + (base_u - raw_u);
    char* AhB = base;
    char* AlB = base + 32768;
    char* WbB = base + 65536;
    float* aux = (float*)(base + 98304);
    float* d1s   = aux;
    float* xyzs  = aux + 384;
    float* bd1s  = aux + 768;
    float* bsumS = aux + 896;
    float* bsumV = aux + 1024;
    float* bg1s  = aux + 1152;
    float* bg2s  = aux + 1280;
    float* part  = aux + 1408;
    uint32_t* tptr = (uint32_t*)(aux + 2432);
    uint32_t mbar_u = smem_to_u32(aux + 2434);

    const int tid = threadIdx.x;
    const int wid = tid >> 5, lid = tid & 31;
    const int p0 = blockIdx.x * 128;
    const int r  = (wid & 3) * 32 + lid;
    const int cb = (wid >> 2) * 64;

    if (blockIdx.x == 0 && tid == 0) g_tc_ok = 1;
    if (wid == 0) { TC_ALLOC(smem_to_u32(tptr), 256); TC_RELINQ(); }
    if (tid == 0) MB_INIT(mbar_u, 1);

    for (int i = tid; i < 384; i += 256) { d1s[i] = d1w[i]; xyzs[i] = xyz[p0 * 3 + i]; }
    if (tid < 128) {
        bd1s[tid]  = d1b[tid];
        bsumS[tid] = g_bs[tid] + d2b[tid];
        bsumV[tid] = g_bv[tid] + d2b[tid];
        bg1s[tid]  = g1b[tid];
        bg2s[tid]  = g2b[tid];
    }
    for (int i = tid * 16; i < 32768; i += 4096)
        *(uint4*)(WbB + i) = *(const uint4*)(g_wimg + IW_D2H + i);
    __syncthreads();
    const uint32_t tmem = *tptr;
    const uint32_t ah_u = base_u;
    const uint64_t dAh = make_desc(ah_u);
    const uint64_t dAl = make_desc(ah_u + 32768);
    const uint64_t dW0 = make_desc(ah_u + 65536);
    const uint64_t dW1 = make_desc(ah_u + 65536 + 16384);

    {
        float x0 = xyzs[r * 3], x1 = xyzs[r * 3 + 1], x2 = xyzs[r * 3 + 2];
        #pragma unroll
        for (int g8 = 0; g8 < 8; g8++) {
            int k0 = cb + g8 * 8;
            float h8[8], l8[8];
            #pragma unroll
            for (int j = 0; j < 8; j++) {
                int c = k0 + j;
                float h = fmaxf(x0 * d1s[c] + x1 * d1s[128 + c] + x2 * d1s[256 + c] + bd1s[c], 0.f);
                splitbf(h, h8[j], l8[j]);
            }
            int off = img2_off(r, k0);
            *(uint4*)(AhB + off) = pk8(h8);
            *(uint4*)(AlB + off) = pk8(l8);
        }
    }
    FENCE_ASYNC(); __syncthreads();

    if (wid == 0 && elect_one_pred()) {
        TC_FENCE_AFTER();
        #pragma unroll
        for (int s = 0; s < 8; s++) mma_bf(tmem + TM_P, dAh + koff(s), dW0 + koff(s), IDESC_BF16, s > 0);
        #pragma unroll
        for (int s = 0; s < 8; s++) mma_bf(tmem + TM_P, dAl + koff(s), dW0 + koff(s), IDESC_BF16, true);
        TC_COMMIT(mbar_u);
    }
    MB_WAIT(mbar_u, 0);

    for (int i = tid * 16; i < 32768; i += 4096)
        *(uint4*)(WbB + i) = *(const uint4*)(g_wimg + IW_D2L + i);
    FENCE_ASYNC(); __syncthreads();
    if (wid == 0 && elect_one_pred()) {
        TC_FENCE_AFTER();
        #pragma unroll
        for (int s = 0; s < 8; s++) mma_bf(tmem + TM_P, dAh + koff(s), dW0 + koff(s), IDESC_BF16, true);
        TC_COMMIT(mbar_u);
    }
    MB_WAIT(mbar_u, 1);

    {
        int fcb = (wid >> 2) * 32;
        const float* fr = feat + (size_t)(p0 + r) * 64 + fcb;
        #pragma unroll
        for (int g8 = 0; g8 < 4; g8++) {
            float4 v0 = *(const float4*)(fr + g8 * 8);
            float4 v1 = *(const float4*)(fr + g8 * 8 + 4);
            float h8[8], l8[8];
            splitbf(v0.x, h8[0], l8[0]); splitbf(v0.y, h8[1], l8[1]);
            splitbf(v0.z, h8[2], l8[2]); splitbf(v0.w, h8[3], l8[3]);
            splitbf(v1.x, h8[4], l8[4]); splitbf(v1.y, h8[5], l8[5]);
            splitbf(v1.z, h8[6], l8[6]); splitbf(v1.w, h8[7], l8[7]);
            int off = img2_off(r, fcb + g8 * 8);
            *(uint4*)(AhB + off) = pk8(h8);
            *(uint4*)(AlB + off) = pk8(l8);
        }
    }
    for (int i = tid * 16; i < 32768; i += 4096)
        *(uint4*)(WbB + i) = *(const uint4*)(g_wimg + IW_WVH + i);
    FENCE_ASYNC(); __syncthreads();

    if (wid == 0 && elect_one_pred()) {
        TC_FENCE_AFTER();
        #pragma unroll
        for (int s = 0; s < 4; s++) mma_bf(tmem + TM_D, dAh + koff(s), dW0 + koff(s), IDESC_BF16, s > 0);
        #pragma unroll
        for (int s = 0; s < 4; s++) mma_bf(tmem + TM_D, dAl + koff(s), dW0 + koff(s), IDESC_BF16, true);
        #pragma unroll
        for (int s = 0; s < 4; s++) mma_bf(tmem + TM_D, dAh + koff(s), dW1 + koff(s), IDESC_BF16, true);
        TC_COMMIT(mbar_u);
    }
    MB_WAIT(mbar_u, 0);
    TC_FENCE_AFTER();

    for (int i = tid * 16; i < 32768; i += 4096)
        *(uint4*)(WbB + i) = *(const uint4*)(g_wimg + IW_WSH + i);
    #pragma unroll
    for (int ch = 0; ch < 2; ch++) {
        int c0 = cb + ch * 32;
        uint32_t pr[32], dr[32];
        LDTM_X32(pr, tmem + TM_P + c0);
        LDTM_X32(dr, tmem + TM_D + c0);
        TC_WAIT_LD();
        float* gvp = g_gv + (size_t)(p0 + r) * 128 + c0;
        #pragma unroll
        for (int g4 = 0; g4 < 8; g4++) {
            float4 o;
            o.x = __uint_as_float(pr[g4*4+0]) + __uint_as_float(dr[g4*4+0]) + bsumV[c0+g4*4+0];
            o.y = __uint_as_float(pr[g4*4+1]) + __uint_as_float(dr[g4*4+1]) + bsumV[c0+g4*4+1];
            o.z = __uint_as_float(pr[g4*4+2]) + __uint_as_float(dr[g4*4+2]) + bsumV[c0+g4*4+2];
            o.w = __uint_as_float(pr[g4*4+3]) + __uint_as_float(dr[g4*4+3]) + bsumV[c0+g4*4+3];
            *(float4*)(gvp + g4 * 4) = o;
        }
    }
    TC_FENCE_BEFORE(); FENCE_ASYNC(); __syncthreads();

    if (wid == 0 && elect_one_pred()) {
        TC_FENCE_AFTER();
        #pragma unroll
        for (int s = 0; s < 4; s++) mma_bf(tmem + TM_D, dAh + koff(s), dW0 + koff(s), IDESC_BF16, s > 0);
        #pragma unroll
        for (int s = 0; s < 4; s++) mma_bf(tmem + TM_D, dAl + koff(s), dW0 + koff(s), IDESC_BF16, true);
        #pragma unroll
        for (int s = 0; s < 4; s++) mma_bf(tmem + TM_D, dAh + koff(s), dW1 + koff(s), IDESC_BF16, true);
        TC_COMMIT(mbar_u);
    }
    MB_WAIT(mbar_u, 1);
    TC_FENCE_AFTER();

    for (int i = tid * 16; i < 32768; i += 4096)
        *(uint4*)(WbB + i) = *(const uint4*)(g_wimg + IW_G1H + i);
    #pragma unroll
    for (int ch = 0; ch < 2; ch++) {
        int c0 = cb + ch * 32;
        uint32_t pr[32], dr[32];
        LDTM_X32(pr, tmem + TM_P + c0);
        LDTM_X32(dr, tmem + TM_D + c0);
        TC_WAIT_LD();
        #pragma unroll
        for (int g8 = 0; g8 < 4; g8++) {
            float h8[8], l8[8];
            #pragma unroll
            for (int j = 0; j < 8; j++) {
                int jj = g8 * 8 + j;
                float s = __uint_as_float(pr[jj]) + __uint_as_float(dr[jj]) + bsumS[c0 + jj];
                splitbf(s, h8[j], l8[j]);
            }
            int off = img2_off(r, c0 + g8 * 8);
            *(uint4*)(AhB + off) = pk8(h8);
            *(uint4*)(AlB + off) = pk8(l8);
        }
    }
    TC_FENCE_BEFORE(); FENCE_ASYNC(); __syncthreads();

    if (wid == 0 && elect_one_pred()) {
        TC_FENCE_AFTER();
        #pragma unroll
        for (int s = 0; s < 8; s++) mma_bf(tmem + TM_P, dAh + koff(s), dW0 + koff(s), IDESC_BF16, s > 0);
        #pragma unroll
        for (int s = 0; s < 8; s++) mma_bf(tmem + TM_P, dAl + koff(s), dW0 + koff(s), IDESC_BF16, true);
        TC_COMMIT(mbar_u);
    }
    MB_WAIT(mbar_u, 0);

    for (int i = tid * 16; i < 32768; i += 4096)
        *(uint4*)(WbB + i) = *(const uint4*)(g_wimg + IW_G1L + i);
    FENCE_ASYNC(); __syncthreads();
    if (wid == 0 && elect_one_pred()) {
        TC_FENCE_AFTER();
        #pragma unroll
        for (int s = 0; s < 8; s++) mma_bf(tmem + TM_P, dAh + koff(s), dW0 + koff(s), IDESC_BF16, true);
        TC_COMMIT(mbar_u);
    }
    MB_WAIT(mbar_u, 1);
    TC_FENCE_AFTER();

    for (int i = tid * 16; i < 32768; i += 4096)
        *(uint4*)(WbB + i) = *(const uint4*)(g_wimg + IW_G2H + i);
    #pragma unroll
    for (int ch = 0; ch < 2; ch++) {
        int c0 = cb + ch * 32;
        uint32_t pr[32];
        LDTM_X32(pr, tmem + TM_P + c0);
        TC_WAIT_LD();
        #pragma unroll
        for (int g8 = 0; g8 < 4; g8++) {
            float h8[8], l8[8];
            #pragma unroll
            for (int j = 0; j < 8; j++) {
                int jj = g8 * 8 + j;
                float h = fmaxf(__uint_as_float(pr[jj]) + bg1s[c0 + jj], 0.f);
                splitbf(h, h8[j], l8[j]);
            }
            int off = img2_off(r, c0 + g8 * 8);
            *(uint4*)(AhB + off) = pk8(h8);
            *(uint4*)(AlB + off) = pk8(l8);
        }
    }
    TC_FENCE_BEFORE(); FENCE_ASYNC(); __syncthreads();

    if (wid == 0 && elect_one_pred()) {
        TC_FENCE_AFTER();
        #pragma unroll
        for (int s = 0; s < 8; s++) mma_bf(tmem + TM_D, dAh + koff(s), dW0 + koff(s), IDESC_BF16, s > 0);
        #pragma unroll
        for (int s = 0; s < 8; s++) mma_bf(tmem + TM_D, dAl + koff(s), dW0 + koff(s), IDESC_BF16, true);
        TC_COMMIT(mbar_u);
    }
    MB_WAIT(mbar_u, 0);

    for (int i = tid * 16; i < 32768; i += 4096)
        *(uint4*)(WbB + i) = *(const uint4*)(g_wimg + IW_G2L + i);
    FENCE_ASYNC(); __syncthreads();
    if (wid == 0 && elect_one_pred()) {
        TC_FENCE_AFTER();
        #pragma unroll
        for (int s = 0; s < 8; s++) mma_bf(tmem + TM_D, dAh + koff(s), dW0 + koff(s), IDESC_BF16, true);
        TC_COMMIT(mbar_u);
    }
    MB_WAIT(mbar_u, 1);
    TC_FENCE_AFTER();

    {
        float* ao = aout + (size_t)(p0 + r) * 128;
        #pragma unroll
        for (int ch = 0; ch < 2; ch++) {
            int c0 = cb + ch * 32;
            uint32_t dr[32];
            LDTM_X32(dr, tmem + TM_D + c0);
            TC_WAIT_LD();
            #pragma unroll
            for (int j = 0; j < 32; j++)
                dr[j] = __float_as_uint((__uint_as_float(dr[j]) + bg2s[c0 + j]) * SCALE_F);
            #pragma unroll
            for (int g4 = 0; g4 < 8; g4++) {
                float4 o;
                o.x = __uint_as_float(dr[g4*4+0]); o.y = __uint_as_float(dr[g4*4+1]);
                o.z = __uint_as_float(dr[g4*4+2]); o.w = __uint_as_float(dr[g4*4+3]);
                *(float4*)(ao + c0 + g4 * 4) = o;
            }
            #pragma unroll
            for (int j = 0; j < 32; j++) {
                float v = __uint_as_float(dr[j]);
                float m = v;
                #pragma unroll
                for (int o = 16; o; o >>= 1) m = fmaxf(m, __shfl_xor_sync(0xffffffffu, m, o));
                float e = __expf(v - m);
                #pragma unroll
                for (int o = 16; o; o >>= 1) e += __shfl_xor_sync(0xffffffffu, e, o);
                if (lid == 0) {
                    part[wid * 128 + (ch * 32 + j) * 2]     = m;
                    part[wid * 128 + (ch * 32 + j) * 2 + 1] = e;
                }
            }
        }
    }
    TC_FENCE_BEFORE();
    __syncthreads();
    if (wid == 0) TC_DEALLOC(tmem, 256);

    if (tid < 128) {
        int c = tid, grp = c >> 6, lc = c & 63;
        float M = -3.4e38f, S = 0.f;
        #pragma unroll
        for (int w = 0; w < 4; w++) {
            int wd = grp * 4 + w;
            float m2 = part[wd * 128 + lc * 2], s2 = part[wd * 128 + lc * 2 + 1];
            float nM = fmaxf(M, m2);
            S = S * __expf(M - nM) + s2 * __expf(m2 - nM);
            M = nM;
        }
        int b = blockIdx.x >> 9, cl = blockIdx.x & 511;
        int o = ((b * 128 + c) * NPART + cl) * 2;
        g_part[o] = M; g_part[o + 1] = S;
    }
#endif // HAS_TC
}

// ---------------- k3_tc: softmax + gate + fc2 on tcgen05 ----------------
#define K3_SMEM_BYTES 100672
__global__ void __launch_bounds__(256, 2) k3_tc(
    const float* __restrict__ feat, const float* __restrict__ fc2b,
    float* __restrict__ res, float* __restrict__ aout)
{
#if HAS_TC
    extern __shared__ char smraw[];
    uint32_t raw_u = smem_to_u32(smraw);
    uint32_t base_u = (raw_u + 1023u) & ~1023u;
    char* base = smraw + (base_u - raw_u);
    char* AhB = base;
    char* AlB = base + 32768;
    char* WbB = base + 65536;
    float* aux = (float*)(base + 98304);
    float* msm = aux;           // 128
    float* rsm = aux + 128;     // 128
    float* fbv = aux + 256;     // 64
    uint32_t* tptr = (uint32_t*)(aux + 320);
    uint32_t mbar_u = smem_to_u32(aux + 322);

    const int tid = threadIdx.x;
    const int wid = tid >> 5, lid = tid & 31;
    const int p0 = blockIdx.x * 128;
    const int b  = blockIdx.x >> 9;
    const int r  = (wid & 3) * 32 + lid;
    const int kh = (wid >> 2) * 64;

    if (wid == 0) { TC_ALLOC(smem_to_u32(tptr), 128); TC_RELINQ(); }
    if (tid == 0) MB_INIT(mbar_u, 1);

    for (int i = tid * 16; i < 32768; i += 4096)
        *(uint4*)(WbB + i) = *(const uint4*)(g_wimg + IW_FCH + i);
    if (tid < 128) {
        msm[tid] = g_ms[(b * 128 + tid) * 2];
        rsm[tid] = g_ms[(b * 128 + tid) * 2 + 1];
    }
    if (tid < 64) fbv[tid] = fc2b[tid];
    __syncthreads();
    const uint32_t tmem = *tptr;
    const uint64_t dAh = make_desc(base_u);
    const uint64_t dAl = make_desc(base_u + 32768);
    const uint64_t dW0 = make_desc(base_u + 65536);
    const uint64_t dW1 = make_desc(base_u + 65536 + 16384);

    // exp + write attn + gate -> bf16 split A image (row r, k = kh..kh+64)
    {
        float* ap = aout + (size_t)(p0 + r) * 128 + kh;
        const float* gp = g_gv + (size_t)(p0 + r) * 128 + kh;
        #pragma unroll
        for (int g8 = 0; g8 < 8; g8++) {
            float4 a0 = *(const float4*)(ap + g8 * 8);
            float4 a1 = *(const float4*)(ap + g8 * 8 + 4);
            float4 v0 = *(const float4*)(gp + g8 * 8);
            float4 v1 = *(const float4*)(gp + g8 * 8 + 4);
            int c = kh + g8 * 8;
            float e[8];
            e[0] = __expf(a0.x - msm[c+0]) * rsm[c+0];
            e[1] = __expf(a0.y - msm[c+1]) * rsm[c+1];
            e[2] = __expf(a0.z - msm[c+2]) * rsm[c+2];
            e[3] = __expf(a0.w - msm[c+3]) * rsm[c+3];
            e[4] = __expf(a1.x - msm[c+4]) * rsm[c+4];
            e[5] = __expf(a1.y - msm[c+5]) * rsm[c+5];
            e[6] = __expf(a1.z - msm[c+6]) * rsm[c+6];
            e[7] = __expf(a1.w - msm[c+7]) * rsm[c+7];
            float4 o0 = { e[0], e[1], e[2], e[3] };
            float4 o1 = { e[4], e[5], e[6], e[7] };
            *(float4*)(ap + g8 * 8)     = o0;
            *(float4*)(ap + g8 * 8 + 4) = o1;
            float gt[8] = { e[0]*v0.x, e[1]*v0.y, e[2]*v0.z, e[3]*v0.w,
                            e[4]*v1.x, e[5]*v1.y, e[6]*v1.z, e[7]*v1.w };
            float h8[8], l8[8];
            #pragma unroll
            for (int j = 0; j < 8; j++) splitbf(gt[j], h8[j], l8[j]);
            int off = img2_off(r, c);
            *(uint4*)(AhB + off) = pk8(h8);
            *(uint4*)(AlB + off) = pk8(l8);
        }
    }
    FENCE_ASYNC(); __syncthreads();

    // D(64) = gated(3 terms) @ fc2
    if (wid == 0 && elect_one_pred()) {
        TC_FENCE_AFTER();
        #pragma unroll
        for (int s = 0; s < 8; s++) mma_bf(tmem, dAh + koff(s), dW0 + koff64(s), IDESC_BF16_64, s > 0);
        #pragma unroll
        for (int s = 0; s < 8; s++) mma_bf(tmem, dAl + koff(s), dW0 + koff64(s), IDESC_BF16_64, true);
        #pragma unroll
        for (int s = 0; s < 8; s++) mma_bf(tmem, dAh + koff(s), dW1 + koff64(s), IDESC_BF16_64, true);
        TC_COMMIT(mbar_u);
    }
    MB_WAIT(mbar_u, 0);
    TC_FENCE_AFTER();

    // out: warp w -> lanes (w&3), cols (w>>2)*32
    {
        int c0 = (wid >> 2) * 32;
        uint32_t dr[32];
        LDTM_X32(dr, tmem + c0);
        TC_WAIT_LD();
        const float* fp = feat + (size_t)(p0 + r) * 64 + c0;
        float* rp = res + (size_t)(p0 + r) * 64 + c0;
        #pragma unroll
        for (int g4 = 0; g4 < 8; g4++) {
            float4 f = *(const float4*)(fp + g4 * 4);
            float4 o;
            o.x = __uint_as_float(dr[g4*4+0]) + fbv[c0+g4*4+0] + f.x;
            o.y = __uint_as_float(dr[g4*4+1]) + fbv[c0+g4*4+1] + f.y;
            o.z = __uint_as_float(dr[g4*4+2]) + fbv[c0+g4*4+2] + f.z;
            o.w = __uint_as_float(dr[g4*4+3]) + fbv[c0+g4*4+3] + f.w;
            *(float4*)(rp + g4 * 4) = o;
        }
    }
    TC_FENCE_BEFORE();
    __syncthreads();
    if (wid == 0) TC_DEALLOC(tmem, 128);
#endif // HAS_TC
}

// ================== FFMA2 fallback path ==================
__device__ __forceinline__ void gemm_tile2(const float* __restrict__ A, int lda,
                                           const float* __restrict__ W, int ldw, int K,
                                           int r0, int c0, float acc[8][8])
{
    unsigned long long acc2[8][4];
    #pragma unroll
    for (int i = 0; i < 8; i++)
        #pragma unroll
        for (int j = 0; j < 4; j++) acc2[i][j] = 0ull;
    #pragma unroll 2
    for (int k = 0; k < K; k += 2) {
        ulonglong2 w00 = *(const ulonglong2*)(W + (size_t)k * ldw + c0);
        ulonglong2 w01 = *(const ulonglong2*)(W + (size_t)k * ldw + c0 + 4);
        ulonglong2 w10 = *(const ulonglong2*)(W + (size_t)(k + 1) * ldw + c0);
        ulonglong2 w11 = *(const ulonglong2*)(W + (size_t)(k + 1) * ldw + c0 + 4);
        #pragma unroll
        for (int i = 0; i < 8; i++) {
            float2 a2 = *(const float2*)(A + (r0 + i) * lda + k);
            unsigned long long a0 = pk2(a2.x, a2.x);
            unsigned long long a1 = pk2(a2.y, a2.y);
            fma2(acc2[i][0], a0, w00.x); fma2(acc2[i][1], a0, w00.y);
            fma2(acc2[i][2], a0, w01.x); fma2(acc2[i][3], a0, w01.y);
            fma2(acc2[i][0], a1, w10.x); fma2(acc2[i][1], a1, w10.y);
            fma2(acc2[i][2], a1, w11.x); fma2(acc2[i][3], a1, w11.y);
        }
    }
    #pragma unroll
    for (int i = 0; i < 8; i++)
        #pragma unroll
        for (int j = 0; j < 4; j++)
            upk2(acc2[i][j], acc[i][2 * j], acc[i][2 * j + 1]);
}

__global__ void __launch_bounds__(256) k1_fb(
    const float* __restrict__ xyz, const float* __restrict__ feat,
    const float* __restrict__ d1w, const float* __restrict__ d1b,
    const float* __restrict__ d2w, const float* __restrict__ d2b,
    const float* __restrict__ g1w, const float* __restrict__ g1b,
    const float* __restrict__ g2w, const float* __restrict__ g2b,
    float* __restrict__ aout)
{
    if (g_tc_ok) return;

    extern __shared__ float smd[];
    float* Wsm = smd;
    float* Pm  = smd + 16384;
    float* Tm  = smd + 32768;
    __shared__ float d1s[384], xyzs[384];
    __shared__ float bd1[DM], bd2[DM], bg1[DM], bg2[DM], bss[DM], bvv[DM];

    const int tid = threadIdx.x;
    const int tx = tid & 15, ty = tid >> 4;
    const int r0 = ty * 8, c0 = tx * 8;
    const int p0 = blockIdx.x * 128;

    for (int i = tid; i < 384; i += 256) { d1s[i] = d1w[i]; xyzs[i] = xyz[p0 * 3 + i]; }
    if (tid < DM) {
        bd1[tid] = d1b[tid]; bd2[tid] = d2b[tid];
        bg1[tid] = g1b[tid]; bg2[tid] = g2b[tid];
        bss[tid] = g_bs[tid]; bvv[tid] = g_bv[tid];
    }
    for (int i = tid * 4; i < 16384; i += 1024)
        *(float4*)(Wsm + i) = *(const float4*)(d2w + i);
    __syncthreads();

    #pragma unroll
    for (int i = 0; i < 8; i++) {
        int p = r0 + i;
        float x0 = xyzs[p * 3], x1 = xyzs[p * 3 + 1], x2 = xyzs[p * 3 + 2];
        #pragma unroll
        for (int j = 0; j < 8; j++) {
            int c = c0 + j;
            float h = x0 * d1s[c] + x1 * d1s[DM + c] + x2 * d1s[2 * DM + c] + bd1[c];
            Tm[p * DM + c] = fmaxf(h, 0.f);
        }
    }
    __syncthreads();

    float acc[8][8];
    gemm_tile2(Tm, DM, Wsm, DM, DM, r0, c0, acc);
    #pragma unroll
    for (int i = 0; i < 8; i++)
        #pragma unroll
        for (int j = 0; j < 8; j++)
            Pm[(r0 + i) * DM + c0 + j] = acc[i][j] + bd2[c0 + j];
    __syncthreads();

    for (int i = tid * 4; i < 8192; i += 1024) {
        *(float4*)(Tm + i)  = *(const float4*)(feat + p0 * 64 + i);
        *(float4*)(Wsm + i) = *(const float4*)(g_Wv + i);
    }
    __syncthreads();

    gemm_tile2(Tm, 64, Wsm, DM, 64, r0, c0, acc);
    #pragma unroll
    for (int i = 0; i < 8; i++)
        #pragma unroll
        for (int j = 0; j < 8; j++)
            g_gv[(size_t)(p0 + r0 + i) * DM + c0 + j] =
                acc[i][j] + bvv[c0 + j] + Pm[(r0 + i) * DM + c0 + j];
    __syncthreads();

    for (int i = tid * 4; i < 8192; i += 1024)
        *(float4*)(Wsm + i) = *(const float4*)(g_Ws + i);
    __syncthreads();

    gemm_tile2(Tm, 64, Wsm, DM, 64, r0, c0, acc);
    #pragma unroll
    for (int i = 0; i < 8; i++)
        #pragma unroll
        for (int j = 0; j < 8; j++) {
            int o = (r0 + i) * DM + c0 + j;
            Pm[o] = acc[i][j] + bss[c0 + j] + Pm[o];
        }
    __syncthreads();

    for (int i = tid * 4; i < 16384; i += 1024)
        *(float4*)(Wsm + i) = *(const float4*)(g1w + i);
    __syncthreads();

    gemm_tile2(Pm, DM, Wsm, DM, DM, r0, c0, acc);
    #pragma unroll
    for (int i = 0; i < 8; i++)
        #pragma unroll
        for (int j = 0; j < 8; j++)
            Tm[(r0 + i) * DM + c0 + j] = fmaxf(acc[i][j] + bg1[c0 + j], 0.f);
    __syncthreads();

    for (int i = tid * 4; i < 16384; i += 1024)
        *(float4*)(Wsm + i) = *(const float4*)(g2w + i);
    __syncthreads();

    gemm_tile2(Tm, DM, Wsm, DM, DM, r0, c0, acc);
    #pragma unroll
    for (int i = 0; i < 8; i++)
        #pragma unroll
        for (int j = 0; j < 8; j++)
            aout[(size_t)(p0 + r0 + i) * DM + c0 + j] =
                (acc[i][j] + bg2[c0 + j]) * SCALE_F;
}

__global__ void k2a_fb(const float* __restrict__ aout)
{
    if (g_tc_ok) return;
    int cl = blockIdx.x, b = blockIdx.y;
    int tid = threadIdx.x;
    int c = tid & 127, half = tid >> 7;
    const float* base = aout + ((size_t)(b * N_ + cl * 128 + half * 64)) * 128 + c;
    float m = -3.4e38f, s = 0.f;
    #pragma unroll 4
    for (int rr = 0; rr < 64; rr++) {
        float a = base[(size_t)rr * 128];
        float nm = fmaxf(m, a);
        s = s * __expf(m - nm) + __expf(a - nm);
        m = nm;
    }
    __shared__ float sm[256][2];
    sm[tid][0] = m; sm[tid][1] = s;
    __syncthreads();
    if (half == 0) {
        float m2 = sm[tid + 128][0], s2 = sm[tid + 128][1];
        float nM = fmaxf(m, m2);
        float S = s * __expf(m - nM) + s2 * __expf(m2 - nM);
        int o = ((b * 128 + c) * NPART + cl) * 2;
        g_part[o] = nM; g_part[o + 1] = S;
    }
}

__global__ void k2b_combine()
{
    int warp = (blockIdx.x * blockDim.x + threadIdx.x) >> 5;
    int lane = threadIdx.x & 31;
    const float* p = g_part + (size_t)warp * NPART * 2;
    float M = -3.4e38f, S = 0.f;
    for (int j = lane; j < NPART; j += 32) {
        float m2 = p[j * 2], s2 = p[j * 2 + 1];
        float nM = fmaxf(M, m2);
        S = S * __expf(M - nM) + s2 * __expf(m2 - nM);
        M = nM;
    }
    #pragma unroll
    for (int o = 16; o; o >>= 1) {
        float m2 = __shfl_xor_sync(0xffffffffu, M, o);
        float s2 = __shfl_xor_sync(0xffffffffu, S, o);
        float nM = fmaxf(M, m2);
        S = S * __expf(M - nM) + s2 * __expf(m2 - nM);
        M = nM;
    }
    if (lane == 0) { g_ms[warp * 2] = M; g_ms[warp * 2 + 1] = 1.f / S; }
}

// ---------------- k3 fallback ----------------
__global__ void __launch_bounds__(256) k3_fb(
    const float* __restrict__ feat,
    const float* __restrict__ fc2w, const float* __restrict__ fc2b,
    float* __restrict__ res, float* __restrict__ aout)
{
    if (g_tc_ok) return;

    extern __shared__ float smd[];
    float* fc2s = smd;
    float* tsm  = smd + 8192;
    __shared__ float msm[DM], rsm[DM], fb[64];

    int tid = threadIdx.x;
    int p0 = blockIdx.x * 128;
    int b = p0 >> 16;

    for (int i = tid * 4; i < 8192; i += 1024)
        *(float4*)(fc2s + i) = *(const float4*)(fc2w + i);
    if (tid < DM) {
        msm[tid] = g_ms[(b * DM + tid) * 2];
        rsm[tid] = g_ms[(b * DM + tid) * 2 + 1];
    }
    if (tid < 64) fb[tid] = fc2b[tid];
    __syncthreads();

    for (int idx = tid; idx < 16384; idx += 256) {
        int c = idx & 127;
        size_t go = (size_t)p0 * DM + idx;
        float a = aout[go];
        float e = __expf(a - msm[c]) * rsm[c];
        aout[go] = e;
        tsm[idx] = e * g_gv[go];
    }
    __syncthreads();

    int tx = tid & 15, ty = tid >> 4;
    int r0 = ty * 8, c0 = tx * 4;
    unsigned long long acc2[8][2];
    #pragma unroll
    for (int i = 0; i < 8; i++) { acc2[i][0] = 0ull; acc2[i][1] = 0ull; }
    #pragma unroll 4
    for (int k = 0; k < DM; k++) {
        ulonglong2 w = *(const ulonglong2*)(fc2s + k * 64 + c0);
        #pragma unroll
        for (int i = 0; i < 8; i++) {
            float a = tsm[(r0 + i) * DM + k];
            unsigned long long aa = pk2(a, a);
            fma2(acc2[i][0], aa, w.x);
            fma2(acc2[i][1], aa, w.y);
        }
    }
    #pragma unroll
    for (int i = 0; i < 8; i++) {
        float v0, v1, v2, v3;
        upk2(acc2[i][0], v0, v1);
        upk2(acc2[i][1], v2, v3);
        size_t ro = (size_t)(p0 + r0 + i) * 64 + c0;
        res[ro + 0] = v0 + fb[c0 + 0] + feat[ro + 0];
        res[ro + 1] = v1 + fb[c0 + 1] + feat[ro + 1];
        res[ro + 2] = v2 + fb[c0 + 2] + feat[ro + 2];
        res[ro + 3] = v3 + fb[c0 + 3] + feat[ro + 3];
    }
}

// ---------------- launch ----------------
extern "C" void kernel_launch(void* const* d_in, const int* in_sizes, int n_in,
                              void* d_out, int out_size)
{
    const float* xyz  = (const float*)d_in[0];
    const float* feat = (const float*)d_in[1];
    const float* fc1w = (const float*)d_in[2];
    const float* fc1b = (const float*)d_in[3];
    const float* fc2w = (const float*)d_in[4];
    const float* fc2b = (const float*)d_in[5];
    const float* d1w  = (const float*)d_in[6];
    const float* d1b  = (const float*)d_in[7];
    const float* d2w  = (const float*)d_in[8];
    const float* d2b  = (const float*)d_in[9];
    const float* g1w  = (const float*)d_in[10];
    const float* g1b  = (const float*)d_in[11];
    const float* g2w  = (const float*)d_in[12];
    const float* g2b  = (const float*)d_in[13];
    const float* wq   = (const float*)d_in[14];
    const float* wk   = (const float*)d_in[15];
    const float* wv   = (const float*)d_in[16];

    float* res  = (float*)d_out;
    float* aout = (float*)d_out + (size_t)NPTS * 64;

    cudaFuncSetAttribute(k1_tc, cudaFuncAttributeMaxDynamicSharedMemorySize, K1_SMEM_BYTES);
    cudaFuncSetAttribute(k3_tc, cudaFuncAttributeMaxDynamicSharedMemorySize, K3_SMEM_BYTES);
    cudaFuncSetAttribute(k1_fb, cudaFuncAttributeMaxDynamicSharedMemorySize, 196608);
    cudaFuncSetAttribute(k3_fb, cudaFuncAttributeMaxDynamicSharedMemorySize, 98304);

    k0_fold<<<32, 256>>>(fc1w, fc1b, wq, wk, wv);
    k0_img<<<288, 256>>>(d2w, g1w, g2w, fc2w);
    k1_tc<<<NPTS / 128, 256, K1_SMEM_BYTES>>>(xyz, feat, d1w, d1b, d2b, g1b, g2b, aout);
    k1_fb<<<NPTS / 128, 256, 196608>>>(xyz, feat, d1w, d1b, d2w, d2b,
                                       g1w, g1b, g2w, g2b, aout);
    dim3 gfb(NPART, B_);
    k2a_fb<<<gfb, 256>>>(aout);
    k2b_combine<<<32, 256>>>();
    k3_tc<<<NPTS / 128, 256, K3_SMEM_BYTES>>>(feat, fc2b, res, aout);
    k3_fb<<<NPTS / 128, 256, 98304>>>(feat, fc2w, fc2b, res, aout);
}

// round 12
// speedup vs baseline: 2.2377x; 1.0071x over previous
#include <cuda_runtime.h>
#include <cuda_bf16.h>
#include <math.h>
#include <cstdint>

#define B_ 2
#define N_ 65536
#define DM 128
#define NPTS (B_*N_)
#define SCALE_F 0.088388347648318441f
#define NPART 512

#if defined(__CUDA_ARCH_FEAT_SM103_ALL) || defined(__CUDA_ARCH_FEAT_SM100_ALL) || defined(__CUDA_ARCH_FEAT_SM101_ALL)
#define HAS_TC 1
#else
#define HAS_TC 0
#endif

// ---------------- device scratch ----------------
__device__ float g_gv[(size_t)NPTS * DM];
__device__ float g_Ws[64 * 128];
__device__ float g_Wv[64 * 128];
__device__ float g_bs[DM];
__device__ float g_bv[DM];
__device__ float g_part[B_ * DM * NPART * 2];
__device__ float g_ms[B_ * DM * 2];
__device__ __align__(128) unsigned char g_wimg[294912];  // bf16 hi/lo weight images
__device__ int g_tc_ok;

#define IW_D2H 0
#define IW_D2L 32768
#define IW_G1H 65536
#define IW_G1L 98304
#define IW_G2H 131072
#define IW_G2L 163840
#define IW_WSH 196608   /* lo at +16384 */
#define IW_WVH 229376   /* lo at +16384 */
#define IW_FCH 262144   /* fc2 (N=64 layout), lo at +16384 */

// ---------------- generic helpers ----------------
__device__ __forceinline__ uint32_t smem_to_u32(const void* p) {
    uint32_t a;
    asm("{ .reg .u64 t; cvta.to.shared.u64 t, %1; cvt.u32.u64 %0, t; }" : "=r"(a) : "l"(p));
    return a;
}
// (row n, col k) byte offset in blocked+SW128 bf16 image, 128 rows
__device__ __forceinline__ int img2_off(int n, int k) {
    int a = (((k >> 6) * 16 + (n >> 3)) << 10) + ((n & 7) << 7) + ((k & 63) << 1);
    return a ^ ((a >> 3) & 0x70);
}
// same, 64 rows (N=64 B operand): 8 atoms per 64-col k-block
__device__ __forceinline__ int img64_off(int n, int k) {
    int a = (((k >> 6) * 8 + (n >> 3)) << 10) + ((n & 7) << 7) + ((k & 63) << 1);
    return a ^ ((a >> 3) & 0x70);
}
__device__ __forceinline__ void splitbf(float v, float& hi, float& lo) {
    hi = __bfloat162float(__float2bfloat16_rn(v));
    lo = v - hi;
}
__device__ __forceinline__ uint32_t pkbf(float lo, float hi) {
    uint32_t r;
    asm("cvt.rn.bf16x2.f32 %0, %1, %2;" : "=r"(r) : "f"(hi), "f"(lo));
    return r;
}
__device__ __forceinline__ uint4 pk8(const float* f) {
    uint4 u;
    u.x = pkbf(f[0], f[1]); u.y = pkbf(f[2], f[3]);
    u.z = pkbf(f[4], f[5]); u.w = pkbf(f[6], f[7]);
    return u;
}
__device__ __forceinline__ unsigned long long pk2(float x, float y) {
    unsigned long long r; asm("mov.b64 %0, {%1, %2};" : "=l"(r) : "f"(x), "f"(y)); return r;
}
__device__ __forceinline__ void fma2(unsigned long long& d, unsigned long long a, unsigned long long b) {
    asm("fma.rn.f32x2 %0, %1, %2, %0;" : "+l"(d) : "l"(a), "l"(b));
}
__device__ __forceinline__ void upk2(unsigned long long v, float& x, float& y) {
    asm("mov.b64 {%0, %1}, %2;" : "=f"(x), "=f"(y) : "l"(v));
}

// ---------------- k0a ----------------
__global__ void k0_fold(const float* __restrict__ fc1w, const float* __restrict__ fc1b,
                        const float* __restrict__ wq, const float* __restrict__ wk,
                        const float* __restrict__ wv)
{
    if (blockIdx.x == 0 && threadIdx.x == 0) g_tc_ok = 0;
    int idx = blockIdx.x * 256 + threadIdx.x;
    int m = idx >> 7, j = idx & 127;
    float as = 0.f, av = 0.f;
    for (int k = 0; k < DM; k++) {
        float f = fc1w[m * DM + k];
        as += f * (wq[k * DM + j] - wk[k * DM + j]);
        av += f * wv[k * DM + j];
    }
    g_Ws[idx] = as; g_Wv[idx] = av;
    if (blockIdx.x == 0 && threadIdx.x < DM) {
        int jj = threadIdx.x;
        float bs = 0.f, bv = 0.f;
        for (int k = 0; k < DM; k++) {
            float fb = fc1b[k];
            bs += fb * (wq[k * DM + jj] - wk[k * DM + jj]);
            bv += fb * wv[k * DM + jj];
        }
        g_bs[jj] = bs; g_bv[jj] = bv;
    }
}

// ---------------- k0b: weight images ----------------
__global__ void k0_img(const float* __restrict__ d2w, const float* __restrict__ g1w,
                       const float* __restrict__ g2w, const float* __restrict__ fc2w)
{
    int t = blockIdx.x * 256 + threadIdx.x;     // 0..73727
    if (t >= 73728) return;
    const float* src; int bh, bl, e;
    if (t < 16384)      { src = d2w;  bh = IW_D2H; bl = IW_D2L;         e = t; }
    else if (t < 32768) { src = g1w;  bh = IW_G1H; bl = IW_G1L;         e = t - 16384; }
    else if (t < 49152) { src = g2w;  bh = IW_G2H; bl = IW_G2L;         e = t - 32768; }
    else if (t < 57344) { src = g_Ws; bh = IW_WSH; bl = IW_WSH + 16384; e = t - 49152; }
    else if (t < 65536) { src = g_Wv; bh = IW_WVH; bl = IW_WVH + 16384; e = t - 57344; }
    else {
        // fc2: [128,64] -> B[n][k] = fc2w[k*64+n], 64-row image
        e = t - 65536;
        int n = e & 63, k = e >> 6;
        float w = fc2w[k * 64 + n];
        __nv_bfloat16 hb = __float2bfloat16_rn(w);
        __nv_bfloat16 lb = __float2bfloat16_rn(w - __bfloat162float(hb));
        int off = img64_off(n, k);
        *(__nv_bfloat16*)(g_wimg + IW_FCH + off) = hb;
        *(__nv_bfloat16*)(g_wimg + IW_FCH + 16384 + off) = lb;
        return;
    }
    int n = e & 127, k = e >> 7;
    float w = src[k * 128 + n];
    __nv_bfloat16 hb = __float2bfloat16_rn(w);
    __nv_bfloat16 lb = __float2bfloat16_rn(w - __bfloat162float(hb));
    int off = img2_off(n, k);
    *(__nv_bfloat16*)(g_wimg + bh + off) = hb;
    *(__nv_bfloat16*)(g_wimg + bl + off) = lb;
}

// ================== tcgen05 machinery ==================
#if HAS_TC
__device__ __forceinline__ uint32_t elect_one_pred() {
    uint32_t p;
    asm volatile("{\n\t.reg .pred p;\n\telect.sync _|p, 0xFFFFFFFF;\n\t"
                 "selp.b32 %0, 1, 0, p;\n\t}" : "=r"(p));
    return p;
}
#define TC_ALLOC(sa, n) \
    asm volatile("tcgen05.alloc.cta_group::1.sync.aligned.shared::cta.b32 [%0], %1;" \
                 :: "r"((uint32_t)(sa)), "r"((uint32_t)(n)) : "memory")
#define TC_RELINQ() \
    asm volatile("tcgen05.relinquish_alloc_permit.cta_group::1.sync.aligned;")
#define TC_DEALLOC(t, n) \
    asm volatile("tcgen05.dealloc.cta_group::1.sync.aligned.b32 %0, %1;" :: "r"(t), "r"((uint32_t)(n)))
#define TC_COMMIT(mb) \
    asm volatile("tcgen05.commit.cta_group::1.mbarrier::arrive::one.shared::cluster.b64 [%0];" \
                 :: "r"((uint32_t)(mb)) : "memory")
#define TC_WAIT_LD()  asm volatile("tcgen05.wait::ld.sync.aligned;" ::: "memory")
#define TC_FENCE_BEFORE() asm volatile("tcgen05.fence::before_thread_sync;" ::: "memory")
#define TC_FENCE_AFTER()  asm volatile("tcgen05.fence::after_thread_sync;" ::: "memory")
#define FENCE_ASYNC() asm volatile("fence.proxy.async.shared::cta;" ::: "memory")
#define MB_INIT(mb, c) \
    asm volatile("mbarrier.init.shared.b64 [%0], %1;" :: "r"((uint32_t)(mb)), "r"((uint32_t)(c)) : "memory")
#define MB_WAIT(mb, ph) do { \
    uint32_t _m = (uint32_t)(mb), _p = (uint32_t)(ph), _d; \
    asm volatile("{\n\t.reg .pred p;\n\t" \
        "mbarrier.try_wait.parity.acquire.cta.shared::cta.b64 p, [%1], %2;\n\t" \
        "selp.b32 %0, 1, 0, p;\n\t}" : "=r"(_d) : "r"(_m), "r"(_p) : "memory"); \
    if (!_d) { \
        asm volatile("{\n\t.reg .pred P1;\n\t" \
            "WL_%=:\n\t" \
            "mbarrier.try_wait.parity.acquire.cta.shared::cta.b64 P1, [%0], %1, 0x989680;\n\t" \
            "@P1 bra.uni WD_%=;\n\t" \
            "bra.uni WL_%=;\n\tWD_%=:\n\t}" :: "r"(_m), "r"(_p) : "memory"); \
    } } while (0)
#define LDTM_X32(r, a) \
    asm volatile("tcgen05.ld.sync.aligned.32x32b.x32.b32 " \
        "{%0, %1, %2, %3, %4, %5, %6, %7, %8, %9, %10, %11, %12, %13, %14, %15, " \
        " %16, %17, %18, %19, %20, %21, %22, %23, %24, %25, %26, %27, %28, %29, %30, %31}, [%32];" \
        : "=r"((r)[0]),  "=r"((r)[1]),  "=r"((r)[2]),  "=r"((r)[3]), \
          "=r"((r)[4]),  "=r"((r)[5]),  "=r"((r)[6]),  "=r"((r)[7]), \
          "=r"((r)[8]),  "=r"((r)[9]),  "=r"((r)[10]), "=r"((r)[11]), \
          "=r"((r)[12]), "=r"((r)[13]), "=r"((r)[14]), "=r"((r)[15]), \
          "=r"((r)[16]), "=r"((r)[17]), "=r"((r)[18]), "=r"((r)[19]), \
          "=r"((r)[20]), "=r"((r)[21]), "=r"((r)[22]), "=r"((r)[23]), \
          "=r"((r)[24]), "=r"((r)[25]), "=r"((r)[26]), "=r"((r)[27]), \
          "=r"((r)[28]), "=r"((r)[29]), "=r"((r)[30]), "=r"((r)[31]) \
        : "r"(a))

__device__ __forceinline__ uint64_t make_desc(uint32_t addr) {
    const uint64_t base = (uint64_t(2) << 61) | (uint64_t(1) << 46)
                        | (uint64_t(64) << 32) | (uint64_t(1) << 16);
    return base | ((uint64_t)(addr >> 4) & 0x3FFF);
}
#define IDESC_BF16   0x8200490u   /* M=128, N=128 */
#define IDESC_BF16_64 0x8100490u  /* M=128, N=64  */
__device__ __forceinline__ void mma_bf(uint32_t d, uint64_t a, uint64_t b, uint32_t idesc, bool en) {
    uint32_t e = en ? 1u : 0u;
    asm volatile("{\n\t.reg .pred p;\n\tsetp.ne.u32 p, %5, 0;\n\t"
        "tcgen05.mma.cta_group::1.kind::f16 [%0], %1, %2, %3, {%4, %4, %4, %4}, p;\n\t}"
        :: "r"(d), "l"(a), "l"(b), "r"(idesc), "r"(0u), "r"(e) : "memory");
}
__device__ __forceinline__ uint64_t koff(int s)   { return (uint64_t)(((s >> 2) << 10) + ((s & 3) << 1)); }
__device__ __forceinline__ uint64_t koff64(int s) { return (uint64_t)(((s >> 2) << 9)  + ((s & 3) << 1)); }
#endif // HAS_TC

#define K1_SMEM_BYTES 109072
#define TM_P  0
#define TM_D  128

__global__ void __launch_bounds__(256, 2) k1_tc(
    const float* __restrict__ xyz, const float* __restrict__ feat,
    const float* __restrict__ d1w, const float* __restrict__ d1b,
    const float* __restrict__ d2b, const float* __restrict__ g1b,
    const float* __restrict__ g2b, float* __restrict__ aout)
{
#if HAS_TC
    extern __shared__ char smraw[];
    uint32_t raw_u = smem_to_u32(smraw);
    uint32_t base_u = (raw_u + 1023u) & ~1023u;
    char* base = smraw + (base_u - raw_u);
    char* AhB = base;
    char* AlB = base + 32768;
    char* WbB = base + 65536;
    float* aux = (float*)(base + 98304);
    float* d1s   = aux;
    float* xyzs  = aux + 384;
    float* bd1s  = aux + 768;
    float* bsumS = aux + 896;
    float* bsumV = aux + 1024;
    float* bg1s  = aux + 1152;
    float* bg2s  = aux + 1280;
    float* part  = aux + 1408;
    uint32_t* tptr = (uint32_t*)(aux + 2432);
    uint32_t mbar_u = smem_to_u32(aux + 2434);

    const int tid = threadIdx.x;
    const int wid = tid >> 5, lid = tid & 31;
    const int p0 = blockIdx.x * 128;
    const int r  = (wid & 3) * 32 + lid;
    const int cb = (wid >> 2) * 64;

    if (blockIdx.x == 0 && tid == 0) g_tc_ok = 1;
    if (wid == 0) { TC_ALLOC(smem_to_u32(tptr), 256); TC_RELINQ(); }
    if (tid == 0) MB_INIT(mbar_u, 1);

    for (int i = tid; i < 384; i += 256) { d1s[i] = d1w[i]; xyzs[i] = xyz[p0 * 3 + i]; }
    if (tid < 128) {
        bd1s[tid]  = d1b[tid];
        bsumS[tid] = g_bs[tid] + d2b[tid];
        bsumV[tid] = g_bv[tid] + d2b[tid];
        bg1s[tid]  = g1b[tid];
        bg2s[tid]  = g2b[tid];
    }
    for (int i = tid * 16; i < 32768; i += 4096)
        *(uint4*)(WbB + i) = *(const uint4*)(g_wimg + IW_D2H + i);
    __syncthreads();
    const uint32_t tmem = *tptr;
    const uint32_t ah_u = base_u;
    const uint64_t dAh = make_desc(ah_u);
    const uint64_t dAl = make_desc(ah_u + 32768);
    const uint64_t dW0 = make_desc(ah_u + 65536);
    const uint64_t dW1 = make_desc(ah_u + 65536 + 16384);

    {
        float x0 = xyzs[r * 3], x1 = xyzs[r * 3 + 1], x2 = xyzs[r * 3 + 2];
        #pragma unroll
        for (int g8 = 0; g8 < 8; g8++) {
            int k0 = cb + g8 * 8;
            float h8[8], l8[8];
            #pragma unroll
            for (int j = 0; j < 8; j++) {
                int c = k0 + j;
                float h = fmaxf(x0 * d1s[c] + x1 * d1s[128 + c] + x2 * d1s[256 + c] + bd1s[c], 0.f);
                splitbf(h, h8[j], l8[j]);
            }
            int off = img2_off(r, k0);
            *(uint4*)(AhB + off) = pk8(h8);
            *(uint4*)(AlB + off) = pk8(l8);
        }
    }
    FENCE_ASYNC(); __syncthreads();

    if (wid == 0 && elect_one_pred()) {
        TC_FENCE_AFTER();
        #pragma unroll
        for (int s = 0; s < 8; s++) mma_bf(tmem + TM_P, dAh + koff(s), dW0 + koff(s), IDESC_BF16, s > 0);
        #pragma unroll
        for (int s = 0; s < 8; s++) mma_bf(tmem + TM_P, dAl + koff(s), dW0 + koff(s), IDESC_BF16, true);
        TC_COMMIT(mbar_u);
    }
    MB_WAIT(mbar_u, 0);

    for (int i = tid * 16; i < 32768; i += 4096)
        *(uint4*)(WbB + i) = *(const uint4*)(g_wimg + IW_D2L + i);
    FENCE_ASYNC(); __syncthreads();
    if (wid == 0 && elect_one_pred()) {
        TC_FENCE_AFTER();
        #pragma unroll
        for (int s = 0; s < 8; s++) mma_bf(tmem + TM_P, dAh + koff(s), dW0 + koff(s), IDESC_BF16, true);
        TC_COMMIT(mbar_u);
    }
    MB_WAIT(mbar_u, 1);

    {
        int fcb = (wid >> 2) * 32;
        const float* fr = feat + (size_t)(p0 + r) * 64 + fcb;
        #pragma unroll
        for (int g8 = 0; g8 < 4; g8++) {
            float4 v0 = *(const float4*)(fr + g8 * 8);
            float4 v1 = *(const float4*)(fr + g8 * 8 + 4);
            float h8[8], l8[8];
            splitbf(v0.x, h8[0], l8[0]); splitbf(v0.y, h8[1], l8[1]);
            splitbf(v0.z, h8[2], l8[2]); splitbf(v0.w, h8[3], l8[3]);
            splitbf(v1.x, h8[4], l8[4]); splitbf(v1.y, h8[5], l8[5]);
            splitbf(v1.z, h8[6], l8[6]); splitbf(v1.w, h8[7], l8[7]);
            int off = img2_off(r, fcb + g8 * 8);
            *(uint4*)(AhB + off) = pk8(h8);
            *(uint4*)(AlB + off) = pk8(l8);
        }
    }
    for (int i = tid * 16; i < 32768; i += 4096)
        *(uint4*)(WbB + i) = *(const uint4*)(g_wimg + IW_WVH + i);
    FENCE_ASYNC(); __syncthreads();

    if (wid == 0 && elect_one_pred()) {
        TC_FENCE_AFTER();
        #pragma unroll
        for (int s = 0; s < 4; s++) mma_bf(tmem + TM_D, dAh + koff(s), dW0 + koff(s), IDESC_BF16, s > 0);
        #pragma unroll
        for (int s = 0; s < 4; s++) mma_bf(tmem + TM_D, dAl + koff(s), dW0 + koff(s), IDESC_BF16, true);
        #pragma unroll
        for (int s = 0; s < 4; s++) mma_bf(tmem + TM_D, dAh + koff(s), dW1 + koff(s), IDESC_BF16, true);
        TC_COMMIT(mbar_u);
    }
    MB_WAIT(mbar_u, 0);
    TC_FENCE_AFTER();

    for (int i = tid * 16; i < 32768; i += 4096)
        *(uint4*)(WbB + i) = *(const uint4*)(g_wimg + IW_WSH + i);
    #pragma unroll
    for (int ch = 0; ch < 2; ch++) {
        int c0 = cb + ch * 32;
        uint32_t pr[32], dr[32];
        LDTM_X32(pr, tmem + TM_P + c0);
        LDTM_X32(dr, tmem + TM_D + c0);
        TC_WAIT_LD();
        float* gvp = g_gv + (size_t)(p0 + r) * 128 + c0;
        #pragma unroll
        for (int g4 = 0; g4 < 8; g4++) {
            float4 o;
            o.x = __uint_as_float(pr[g4*4+0]) + __uint_as_float(dr[g4*4+0]) + bsumV[c0+g4*4+0];
            o.y = __uint_as_float(pr[g4*4+1]) + __uint_as_float(dr[g4*4+1]) + bsumV[c0+g4*4+1];
            o.z = __uint_as_float(pr[g4*4+2]) + __uint_as_float(dr[g4*4+2]) + bsumV[c0+g4*4+2];
            o.w = __uint_as_float(pr[g4*4+3]) + __uint_as_float(dr[g4*4+3]) + bsumV[c0+g4*4+3];
            *(float4*)(gvp + g4 * 4) = o;
        }
    }
    TC_FENCE_BEFORE(); FENCE_ASYNC(); __syncthreads();

    if (wid == 0 && elect_one_pred()) {
        TC_FENCE_AFTER();
        #pragma unroll
        for (int s = 0; s < 4; s++) mma_bf(tmem + TM_D, dAh + koff(s), dW0 + koff(s), IDESC_BF16, s > 0);
        #pragma unroll
        for (int s = 0; s < 4; s++) mma_bf(tmem + TM_D, dAl + koff(s), dW0 + koff(s), IDESC_BF16, true);
        #pragma unroll
        for (int s = 0; s < 4; s++) mma_bf(tmem + TM_D, dAh + koff(s), dW1 + koff(s), IDESC_BF16, true);
        TC_COMMIT(mbar_u);
    }
    MB_WAIT(mbar_u, 1);
    TC_FENCE_AFTER();

    for (int i = tid * 16; i < 32768; i += 4096)
        *(uint4*)(WbB + i) = *(const uint4*)(g_wimg + IW_G1H + i);
    #pragma unroll
    for (int ch = 0; ch < 2; ch++) {
        int c0 = cb + ch * 32;
        uint32_t pr[32], dr[32];
        LDTM_X32(pr, tmem + TM_P + c0);
        LDTM_X32(dr, tmem + TM_D + c0);
        TC_WAIT_LD();
        #pragma unroll
        for (int g8 = 0; g8 < 4; g8++) {
            float h8[8], l8[8];
            #pragma unroll
            for (int j = 0; j < 8; j++) {
                int jj = g8 * 8 + j;
                float s = __uint_as_float(pr[jj]) + __uint_as_float(dr[jj]) + bsumS[c0 + jj];
                splitbf(s, h8[j], l8[j]);
            }
            int off = img2_off(r, c0 + g8 * 8);
            *(uint4*)(AhB + off) = pk8(h8);
            *(uint4*)(AlB + off) = pk8(l8);
        }
    }
    TC_FENCE_BEFORE(); FENCE_ASYNC(); __syncthreads();

    if (wid == 0 && elect_one_pred()) {
        TC_FENCE_AFTER();
        #pragma unroll
        for (int s = 0; s < 8; s++) mma_bf(tmem + TM_P, dAh + koff(s), dW0 + koff(s), IDESC_BF16, s > 0);
        #pragma unroll
        for (int s = 0; s < 8; s++) mma_bf(tmem + TM_P, dAl + koff(s), dW0 + koff(s), IDESC_BF16, true);
        TC_COMMIT(mbar_u);
    }
    MB_WAIT(mbar_u, 0);

    for (int i = tid * 16; i < 32768; i += 4096)
        *(uint4*)(WbB + i) = *(const uint4*)(g_wimg + IW_G1L + i);
    FENCE_ASYNC(); __syncthreads();
    if (wid == 0 && elect_one_pred()) {
        TC_FENCE_AFTER();
        #pragma unroll
        for (int s = 0; s < 8; s++) mma_bf(tmem + TM_P, dAh + koff(s), dW0 + koff(s), IDESC_BF16, true);
        TC_COMMIT(mbar_u);
    }
    MB_WAIT(mbar_u, 1);
    TC_FENCE_AFTER();

    for (int i = tid * 16; i < 32768; i += 4096)
        *(uint4*)(WbB + i) = *(const uint4*)(g_wimg + IW_G2H + i);
    #pragma unroll
    for (int ch = 0; ch < 2; ch++) {
        int c0 = cb + ch * 32;
        uint32_t pr[32];
        LDTM_X32(pr, tmem + TM_P + c0);
        TC_WAIT_LD();
        #pragma unroll
        for (int g8 = 0; g8 < 4; g8++) {
            float h8[8], l8[8];
            #pragma unroll
            for (int j = 0; j < 8; j++) {
                int jj = g8 * 8 + j;
                float h = fmaxf(__uint_as_float(pr[jj]) + bg1s[c0 + jj], 0.f);
                splitbf(h, h8[j], l8[j]);
            }
            int off = img2_off(r, c0 + g8 * 8);
            *(uint4*)(AhB + off) = pk8(h8);
            *(uint4*)(AlB + off) = pk8(l8);
        }
    }
    TC_FENCE_BEFORE(); FENCE_ASYNC(); __syncthreads();

    if (wid == 0 && elect_one_pred()) {
        TC_FENCE_AFTER();
        #pragma unroll
        for (int s = 0; s < 8; s++) mma_bf(tmem + TM_D, dAh + koff(s), dW0 + koff(s), IDESC_BF16, s > 0);
        #pragma unroll
        for (int s = 0; s < 8; s++) mma_bf(tmem + TM_D, dAl + koff(s), dW0 + koff(s), IDESC_BF16, true);
        TC_COMMIT(mbar_u);
    }
    MB_WAIT(mbar_u, 0);

    for (int i = tid * 16; i < 32768; i += 4096)
        *(uint4*)(WbB + i) = *(const uint4*)(g_wimg + IW_G2L + i);
    FENCE_ASYNC(); __syncthreads();
    if (wid == 0 && elect_one_pred()) {
        TC_FENCE_AFTER();
        #pragma unroll
        for (int s = 0; s < 8; s++) mma_bf(tmem + TM_D, dAh + koff(s), dW0 + koff(s), IDESC_BF16, true);
        TC_COMMIT(mbar_u);
    }
    MB_WAIT(mbar_u, 1);
    TC_FENCE_AFTER();

    {
        float* ao = aout + (size_t)(p0 + r) * 128;
        #pragma unroll
        for (int ch = 0; ch < 2; ch++) {
            int c0 = cb + ch * 32;
            uint32_t dr[32];
            LDTM_X32(dr, tmem + TM_D + c0);
            TC_WAIT_LD();
            #pragma unroll
            for (int j = 0; j < 32; j++)
                dr[j] = __float_as_uint((__uint_as_float(dr[j]) + bg2s[c0 + j]) * SCALE_F);
            #pragma unroll
            for (int g4 = 0; g4 < 8; g4++) {
                float4 o;
                o.x = __uint_as_float(dr[g4*4+0]); o.y = __uint_as_float(dr[g4*4+1]);
                o.z = __uint_as_float(dr[g4*4+2]); o.w = __uint_as_float(dr[g4*4+3]);
                *(float4*)(ao + c0 + g4 * 4) = o;
            }
            #pragma unroll
            for (int j = 0; j < 32; j++) {
                float v = __uint_as_float(dr[j]);
                float m = v;
                #pragma unroll
                for (int o = 16; o; o >>= 1) m = fmaxf(m, __shfl_xor_sync(0xffffffffu, m, o));
                float e = __expf(v - m);
                #pragma unroll
                for (int o = 16; o; o >>= 1) e += __shfl_xor_sync(0xffffffffu, e, o);
                if (lid == 0) {
                    part[wid * 128 + (ch * 32 + j) * 2]     = m;
                    part[wid * 128 + (ch * 32 + j) * 2 + 1] = e;
                }
            }
        }
    }
    TC_FENCE_BEFORE();
    __syncthreads();
    if (wid == 0) TC_DEALLOC(tmem, 256);

    if (tid < 128) {
        int c = tid, grp = c >> 6, lc = c & 63;
        float M = -3.4e38f, S = 0.f;
        #pragma unroll
        for (int w = 0; w < 4; w++) {
            int wd = grp * 4 + w;
            float m2 = part[wd * 128 + lc * 2], s2 = part[wd * 128 + lc * 2 + 1];
            float nM = fmaxf(M, m2);
            S = S * __expf(M - nM) + s2 * __expf(m2 - nM);
            M = nM;
        }
        int b = blockIdx.x >> 9, cl = blockIdx.x & 511;
        int o = ((b * 128 + c) * NPART + cl) * 2;
        g_part[o] = M; g_part[o + 1] = S;
    }
#endif // HAS_TC
}

// ---------------- k3_tc: softmax + gate + fc2 on tcgen05 ----------------
#define K3_SMEM_BYTES 100672
__global__ void __launch_bounds__(256, 2) k3_tc(
    const float* __restrict__ feat, const float* __restrict__ fc2b,
    float* __restrict__ res, float* __restrict__ aout)
{
#if HAS_TC
    extern __shared__ char smraw[];
    uint32_t raw_u = smem_to_u32(smraw);
    uint32_t base_u = (raw_u + 1023u) & ~1023u;
    char* base = smraw + (base_u - raw_u);
    char* AhB = base;
    char* AlB = base + 32768;
    char* WbB = base + 65536;
    float* aux = (float*)(base + 98304);
    float* msm = aux;           // 128
    float* rsm = aux + 128;     // 128
    float* fbv = aux + 256;     // 64
    uint32_t* tptr = (uint32_t*)(aux + 320);
    uint32_t mbar_u = smem_to_u32(aux + 322);

    const int tid = threadIdx.x;
    const int wid = tid >> 5, lid = tid & 31;
    const int p0 = blockIdx.x * 128;
    const int b  = blockIdx.x >> 9;
    const int r  = (wid & 3) * 32 + lid;
    const int kh = (wid >> 2) * 64;

    if (wid == 0) { TC_ALLOC(smem_to_u32(tptr), 128); TC_RELINQ(); }
    if (tid == 0) MB_INIT(mbar_u, 1);

    for (int i = tid * 16; i < 32768; i += 4096)
        *(uint4*)(WbB + i) = *(const uint4*)(g_wimg + IW_FCH + i);
    if (tid < 128) {
        msm[tid] = g_ms[(b * 128 + tid) * 2];
        rsm[tid] = g_ms[(b * 128 + tid) * 2 + 1];
    }
    if (tid < 64) fbv[tid] = fc2b[tid];
    __syncthreads();
    const uint32_t tmem = *tptr;
    const uint64_t dAh = make_desc(base_u);
    const uint64_t dAl = make_desc(base_u + 32768);
    const uint64_t dW0 = make_desc(base_u + 65536);
    const uint64_t dW1 = make_desc(base_u + 65536 + 16384);

    // exp + write attn + gate -> bf16 split A image (row r, k = kh..kh+64)
    {
        float* ap = aout + (size_t)(p0 + r) * 128 + kh;
        const float* gp = g_gv + (size_t)(p0 + r) * 128 + kh;
        #pragma unroll
        for (int g8 = 0; g8 < 8; g8++) {
            float4 a0 = *(const float4*)(ap + g8 * 8);
            float4 a1 = *(const float4*)(ap + g8 * 8 + 4);
            float4 v0 = *(const float4*)(gp + g8 * 8);
            float4 v1 = *(const float4*)(gp + g8 * 8 + 4);
            int c = kh + g8 * 8;
            float e[8];
            e[0] = __expf(a0.x - msm[c+0]) * rsm[c+0];
            e[1] = __expf(a0.y - msm[c+1]) * rsm[c+1];
            e[2] = __expf(a0.z - msm[c+2]) * rsm[c+2];
            e[3] = __expf(a0.w - msm[c+3]) * rsm[c+3];
            e[4] = __expf(a1.x - msm[c+4]) * rsm[c+4];
            e[5] = __expf(a1.y - msm[c+5]) * rsm[c+5];
            e[6] = __expf(a1.z - msm[c+6]) * rsm[c+6];
            e[7] = __expf(a1.w - msm[c+7]) * rsm[c+7];
            float4 o0 = { e[0], e[1], e[2], e[3] };
            float4 o1 = { e[4], e[5], e[6], e[7] };
            *(float4*)(ap + g8 * 8)     = o0;
            *(float4*)(ap + g8 * 8 + 4) = o1;
            float gt[8] = { e[0]*v0.x, e[1]*v0.y, e[2]*v0.z, e[3]*v0.w,
                            e[4]*v1.x, e[5]*v1.y, e[6]*v1.z, e[7]*v1.w };
            float h8[8], l8[8];
            #pragma unroll
            for (int j = 0; j < 8; j++) splitbf(gt[j], h8[j], l8[j]);
            int off = img2_off(r, c);
            *(uint4*)(AhB + off) = pk8(h8);
            *(uint4*)(AlB + off) = pk8(l8);
        }
    }
    FENCE_ASYNC(); __syncthreads();

    // D(64) = gated(3 terms) @ fc2
    if (wid == 0 && elect_one_pred()) {
        TC_FENCE_AFTER();
        #pragma unroll
        for (int s = 0; s < 8; s++) mma_bf(tmem, dAh + koff(s), dW0 + koff64(s), IDESC_BF16_64, s > 0);
        #pragma unroll
        for (int s = 0; s < 8; s++) mma_bf(tmem, dAl + koff(s), dW0 + koff64(s), IDESC_BF16_64, true);
        #pragma unroll
        for (int s = 0; s < 8; s++) mma_bf(tmem, dAh + koff(s), dW1 + koff64(s), IDESC_BF16_64, true);
        TC_COMMIT(mbar_u);
    }
    MB_WAIT(mbar_u, 0);
    TC_FENCE_AFTER();

    // out: warp w -> lanes (w&3), cols (w>>2)*32
    {
        int c0 = (wid >> 2) * 32;
        uint32_t dr[32];
        LDTM_X32(dr, tmem + c0);
        TC_WAIT_LD();
        const float* fp = feat + (size_t)(p0 + r) * 64 + c0;
        float* rp = res + (size_t)(p0 + r) * 64 + c0;
        #pragma unroll
        for (int g4 = 0; g4 < 8; g4++) {
            float4 f = *(const float4*)(fp + g4 * 4);
            float4 o;
            o.x = __uint_as_float(dr[g4*4+0]) + fbv[c0+g4*4+0] + f.x;
            o.y = __uint_as_float(dr[g4*4+1]) + fbv[c0+g4*4+1] + f.y;
            o.z = __uint_as_float(dr[g4*4+2]) + fbv[c0+g4*4+2] + f.z;
            o.w = __uint_as_float(dr[g4*4+3]) + fbv[c0+g4*4+3] + f.w;
            *(float4*)(rp + g4 * 4) = o;
        }
    }
    TC_FENCE_BEFORE();
    __syncthreads();
    if (wid == 0) TC_DEALLOC(tmem, 128);
#endif // HAS_TC
}

// ================== FFMA2 fallback path ==================
__device__ __forceinline__ void gemm_tile2(const float* __restrict__ A, int lda,
                                           const float* __restrict__ W, int ldw, int K,
                                           int r0, int c0, float acc[8][8])
{
    unsigned long long acc2[8][4];
    #pragma unroll
    for (int i = 0; i < 8; i++)
        #pragma unroll
        for (int j = 0; j < 4; j++) acc2[i][j] = 0ull;
    #pragma unroll 2
    for (int k = 0; k < K; k += 2) {
        ulonglong2 w00 = *(const ulonglong2*)(W + (size_t)k * ldw + c0);
        ulonglong2 w01 = *(const ulonglong2*)(W + (size_t)k * ldw + c0 + 4);
        ulonglong2 w10 = *(const ulonglong2*)(W + (size_t)(k + 1) * ldw + c0);
        ulonglong2 w11 = *(const ulonglong2*)(W + (size_t)(k + 1) * ldw + c0 + 4);
        #pragma unroll
        for (int i = 0; i < 8; i++) {
            float2 a2 = *(const float2*)(A + (r0 + i) * lda + k);
            unsigned long long a0 = pk2(a2.x, a2.x);
            unsigned long long a1 = pk2(a2.y, a2.y);
            fma2(acc2[i][0], a0, w00.x); fma2(acc2[i][1], a0, w00.y);
            fma2(acc2[i][2], a0, w01.x); fma2(acc2[i][3], a0, w01.y);
            fma2(acc2[i][0], a1, w10.x); fma2(acc2[i][1], a1, w10.y);
            fma2(acc2[i][2], a1, w11.x); fma2(acc2[i][3], a1, w11.y);
        }
    }
    #pragma unroll
    for (int i = 0; i < 8; i++)
        #pragma unroll
        for (int j = 0; j < 4; j++)
            upk2(acc2[i][j], acc[i][2 * j], acc[i][2 * j + 1]);
}

__global__ void __launch_bounds__(256) k1_fb(
    const float* __restrict__ xyz, const float* __restrict__ feat,
    const float* __restrict__ d1w, const float* __restrict__ d1b,
    const float* __restrict__ d2w, const float* __restrict__ d2b,
    const float* __restrict__ g1w, const float* __restrict__ g1b,
    const float* __restrict__ g2w, const float* __restrict__ g2b,
    float* __restrict__ aout)
{
    if (g_tc_ok) return;

    extern __shared__ float smd[];
    float* Wsm = smd;
    float* Pm  = smd + 16384;
    float* Tm  = smd + 32768;
    __shared__ float d1s[384], xyzs[384];
    __shared__ float bd1[DM], bd2[DM], bg1[DM], bg2[DM], bss[DM], bvv[DM];

    const int tid = threadIdx.x;
    const int tx = tid & 15, ty = tid >> 4;
    const int r0 = ty * 8, c0 = tx * 8;
    const int p0 = blockIdx.x * 128;

    for (int i = tid; i < 384; i += 256) { d1s[i] = d1w[i]; xyzs[i] = xyz[p0 * 3 + i]; }
    if (tid < DM) {
        bd1[tid] = d1b[tid]; bd2[tid] = d2b[tid];
        bg1[tid] = g1b[tid]; bg2[tid] = g2b[tid];
        bss[tid] = g_bs[tid]; bvv[tid] = g_bv[tid];
    }
    for (int i = tid * 4; i < 16384; i += 1024)
        *(float4*)(Wsm + i) = *(const float4*)(d2w + i);
    __syncthreads();

    #pragma unroll
    for (int i = 0; i < 8; i++) {
        int p = r0 + i;
        float x0 = xyzs[p * 3], x1 = xyzs[p * 3 + 1], x2 = xyzs[p * 3 + 2];
        #pragma unroll
        for (int j = 0; j < 8; j++) {
            int c = c0 + j;
            float h = x0 * d1s[c] + x1 * d1s[DM + c] + x2 * d1s[2 * DM + c] + bd1[c];
            Tm[p * DM + c] = fmaxf(h, 0.f);
        }
    }
    __syncthreads();

    float acc[8][8];
    gemm_tile2(Tm, DM, Wsm, DM, DM, r0, c0, acc);
    #pragma unroll
    for (int i = 0; i < 8; i++)
        #pragma unroll
        for (int j = 0; j < 8; j++)
            Pm[(r0 + i) * DM + c0 + j] = acc[i][j] + bd2[c0 + j];
    __syncthreads();

    for (int i = tid * 4; i < 8192; i += 1024) {
        *(float4*)(Tm + i)  = *(const float4*)(feat + p0 * 64 + i);
        *(float4*)(Wsm + i) = *(const float4*)(g_Wv + i);
    }
    __syncthreads();

    gemm_tile2(Tm, 64, Wsm, DM, 64, r0, c0, acc);
    #pragma unroll
    for (int i = 0; i < 8; i++)
        #pragma unroll
        for (int j = 0; j < 8; j++)
            g_gv[(size_t)(p0 + r0 + i) * DM + c0 + j] =
                acc[i][j] + bvv[c0 + j] + Pm[(r0 + i) * DM + c0 + j];
    __syncthreads();

    for (int i = tid * 4; i < 8192; i += 1024)
        *(float4*)(Wsm + i) = *(const float4*)(g_Ws + i);
    __syncthreads();

    gemm_tile2(Tm, 64, Wsm, DM, 64, r0, c0, acc);
    #pragma unroll
    for (int i = 0; i < 8; i++)
        #pragma unroll
        for (int j = 0; j < 8; j++) {
            int o = (r0 + i) * DM + c0 + j;
            Pm[o] = acc[i][j] + bss[c0 + j] + Pm[o];
        }
    __syncthreads();

    for (int i = tid * 4; i < 16384; i += 1024)
        *(float4*)(Wsm + i) = *(const float4*)(g1w + i);
    __syncthreads();

    gemm_tile2(Pm, DM, Wsm, DM, DM, r0, c0, acc);
    #pragma unroll
    for (int i = 0; i < 8; i++)
        #pragma unroll
        for (int j = 0; j < 8; j++)
            Tm[(r0 + i) * DM + c0 + j] = fmaxf(acc[i][j] + bg1[c0 + j], 0.f);
    __syncthreads();

    for (int i = tid * 4; i < 16384; i += 1024)
        *(float4*)(Wsm + i) = *(const float4*)(g2w + i);
    __syncthreads();

    gemm_tile2(Tm, DM, Wsm, DM, DM, r0, c0, acc);
    #pragma unroll
    for (int i = 0; i < 8; i++)
        #pragma unroll
        for (int j = 0; j < 8; j++)
            aout[(size_t)(p0 + r0 + i) * DM + c0 + j] =
                (acc[i][j] + bg2[c0 + j]) * SCALE_F;
}

__global__ void k2a_fb(const float* __restrict__ aout)
{
    if (g_tc_ok) return;
    int cl = blockIdx.x, b = blockIdx.y;
    int tid = threadIdx.x;
    int c = tid & 127, half = tid >> 7;
    const float* base = aout + ((size_t)(b * N_ + cl * 128 + half * 64)) * 128 + c;
    float m = -3.4e38f, s = 0.f;
    #pragma unroll 4
    for (int rr = 0; rr < 64; rr++) {
        float a = base[(size_t)rr * 128];
        float nm = fmaxf(m, a);
        s = s * __expf(m - nm) + __expf(a - nm);
        m = nm;
    }
    __shared__ float sm[256][2];
    sm[tid][0] = m; sm[tid][1] = s;
    __syncthreads();
    if (half == 0) {
        float m2 = sm[tid + 128][0], s2 = sm[tid + 128][1];
        float nM = fmaxf(m, m2);
        float S = s * __expf(m - nM) + s2 * __expf(m2 - nM);
        int o = ((b * 128 + c) * NPART + cl) * 2;
        g_part[o] = nM; g_part[o + 1] = S;
    }
}

__global__ void k2b_combine()
{
    int warp = (blockIdx.x * blockDim.x + threadIdx.x) >> 5;
    int lane = threadIdx.x & 31;
    const float* p = g_part + (size_t)warp * NPART * 2;
    float M = -3.4e38f, S = 0.f;
    for (int j = lane; j < NPART; j += 32) {
        float m2 = p[j * 2], s2 = p[j * 2 + 1];
        float nM = fmaxf(M, m2);
        S = S * __expf(M - nM) + s2 * __expf(m2 - nM);
        M = nM;
    }
    #pragma unroll
    for (int o = 16; o; o >>= 1) {
        float m2 = __shfl_xor_sync(0xffffffffu, M, o);
        float s2 = __shfl_xor_sync(0xffffffffu, S, o);
        float nM = fmaxf(M, m2);
        S = S * __expf(M - nM) + s2 * __expf(m2 - nM);
        M = nM;
    }
    if (lane == 0) { g_ms[warp * 2] = M; g_ms[warp * 2 + 1] = 1.f / S; }
}

// ---------------- k3 fallback ----------------
__global__ void __launch_bounds__(256) k3_fb(
    const float* __restrict__ feat,
    const float* __restrict__ fc2w, const float* __restrict__ fc2b,
    float* __restrict__ res, float* __restrict__ aout)
{
    if (g_tc_ok) return;

    extern __shared__ float smd[];
    float* fc2s = smd;
    float* tsm  = smd + 8192;
    __shared__ float msm[DM], rsm[DM], fb[64];

    int tid = threadIdx.x;
    int p0 = blockIdx.x * 128;
    int b = p0 >> 16;

    for (int i = tid * 4; i < 8192; i += 1024)
        *(float4*)(fc2s + i) = *(const float4*)(fc2w + i);
    if (tid < DM) {
        msm[tid] = g_ms[(b * DM + tid) * 2];
        rsm[tid] = g_ms[(b * DM + tid) * 2 + 1];
    }
    if (tid < 64) fb[tid] = fc2b[tid];
    __syncthreads();

    for (int idx = tid; idx < 16384; idx += 256) {
        int c = idx & 127;
        size_t go = (size_t)p0 * DM + idx;
        float a = aout[go];
        float e = __expf(a - msm[c]) * rsm[c];
        aout[go] = e;
        tsm[idx] = e * g_gv[go];
    }
    __syncthreads();

    int tx = tid & 15, ty = tid >> 4;
    int r0 = ty * 8, c0 = tx * 4;
    unsigned long long acc2[8][2];
    #pragma unroll
    for (int i = 0; i < 8; i++) { acc2[i][0] = 0ull; acc2[i][1] = 0ull; }
    #pragma unroll 4
    for (int k = 0; k < DM; k++) {
        ulonglong2 w = *(const ulonglong2*)(fc2s + k * 64 + c0);
        #pragma unroll
        for (int i = 0; i < 8; i++) {
            float a = tsm[(r0 + i) * DM + k];
            unsigned long long aa = pk2(a, a);
            fma2(acc2[i][0], aa, w.x);
            fma2(acc2[i][1], aa, w.y);
        }
    }
    #pragma unroll
    for (int i = 0; i < 8; i++) {
        float v0, v1, v2, v3;
        upk2(acc2[i][0], v0, v1);
        upk2(acc2[i][1], v2, v3);
        size_t ro = (size_t)(p0 + r0 + i) * 64 + c0;
        res[ro + 0] = v0 + fb[c0 + 0] + feat[ro + 0];
        res[ro + 1] = v1 + fb[c0 + 1] + feat[ro + 1];
        res[ro + 2] = v2 + fb[c0 + 2] + feat[ro + 2];
        res[ro + 3] = v3 + fb[c0 + 3] + feat[ro + 3];
    }
}

// ---------------- launch ----------------
extern "C" void kernel_launch(void* const* d_in, const int* in_sizes, int n_in,
                              void* d_out, int out_size)
{
    const float* xyz  = (const float*)d_in[0];
    const float* feat = (const float*)d_in[1];
    const float* fc1w = (const float*)d_in[2];
    const float* fc1b = (const float*)d_in[3];
    const float* fc2w = (const float*)d_in[4];
    const float* fc2b = (const float*)d_in[5];
    const float* d1w  = (const float*)d_in[6];
    const float* d1b  = (const float*)d_in[7];
    const float* d2w  = (const float*)d_in[8];
    const float* d2b  = (const float*)d_in[9];
    const float* g1w  = (const float*)d_in[10];
    const float* g1b  = (const float*)d_in[11];
    const float* g2w  = (const float*)d_in[12];
    const float* g2b  = (const float*)d_in[13];
    const float* wq   = (const float*)d_in[14];
    const float* wk   = (const float*)d_in[15];
    const float* wv   = (const float*)d_in[16];

    float* res  = (float*)d_out;
    float* aout = (float*)d_out + (size_t)NPTS * 64;

    cudaFuncSetAttribute(k1_tc, cudaFuncAttributeMaxDynamicSharedMemorySize, K1_SMEM_BYTES);
    cudaFuncSetAttribute(k3_tc, cudaFuncAttributeMaxDynamicSharedMemorySize, K3_SMEM_BYTES);
    cudaFuncSetAttribute(k1_fb, cudaFuncAttributeMaxDynamicSharedMemorySize, 196608);
    cudaFuncSetAttribute(k3_fb, cudaFuncAttributeMaxDynamicSharedMemorySize, 98304);

    k0_fold<<<32, 256>>>(fc1w, fc1b, wq, wk, wv);
    k0_img<<<288, 256>>>(d2w, g1w, g2w, fc2w);
    k1_tc<<<NPTS / 128, 256, K1_SMEM_BYTES>>>(xyz, feat, d1w, d1b, d2b, g1b, g2b, aout);
    k1_fb<<<NPTS / 128, 256, 196608>>>(xyz, feat, d1w, d1b, d2w, d2b,
                                       g1w, g1b, g2w, g2b, aout);
    dim3 gfb(NPART, B_);
    k2a_fb<<<gfb, 256>>>(aout);
    k2b_combine<<<32, 256>>>();
    k3_tc<<<NPTS / 128, 256, K3_SMEM_BYTES>>>(feat, fc2b, res, aout);
    k3_fb<<<NPTS / 128, 256, 98304>>>(feat, fc2w, fc2b, res, aout);
}